// round 9
// baseline (speedup 1.0000x reference)
#include <cuda_runtime.h>
#include <math.h>

#define T_STEPS 300
#define DIN 39
#define H1D 35
#define H1P 36          // padded layer-1 units (unit 35 = dummy zeros)
#define H2D 30
#define H2P 32          // padded layer-2 units (units 30,31 = dummy zeros)
#define G1 140
#define G1P 144         // 36 units * 4 gates
#define G2 120
#define G2P 128         // 32 units * 4 gates
#define K1 74
#define K2 65
#define BT 64
#define BTP 68
#define NT 864          // 18 L1 warps + 8 L2 warps + 1 stager warp
#define N_L1 576
#define N_L12 832       // L1 + L2 threads
#define BATCH 4096
#define NBLK (BATCH/BT)

typedef unsigned long long ull;

// ---- shared memory layout (float offsets) ----
#define OFF_W1D 0                          // 74*288 = 21312 (dup, unit-major, padded)
#define OFF_W2D (OFF_W1D + K1*2*G1P)       // 21312, size 65*256 = 16640
#define OFF_B1  (OFF_W2D + K2*2*G2P)       // 37952, 144
#define OFF_B2  (OFF_B1 + G1P)             // 38096, 128
#define OFF_X   (OFF_B2 + G2P)             // 38224, 2*39*68 = 5304
#define OFF_H1  (OFF_X + 2*DIN*BTP)        // 43528, 2*36*68 = 4896
#define OFF_H2  (OFF_H1 + 2*H1P*BTP)       // 48424, 2*32*68 = 4352
#define SM_FLOATS (OFF_H2 + 2*H2P*BTP)     // 52776 floats = 211104 B

#define X_BUF  (DIN*BTP)
#define H1_BUF (H1P*BTP)
#define H2_BUF (H2P*BTP)

// scratch: LSTM hidden states [T][60][B]  (fw units [0,30), bw [30,60))
__device__ float g_hbuf[(size_t)BATCH * T_STEPS * 60];
// scratch: transposed input [T][D][B]
__device__ float g_xT[(size_t)T_STEPS * DIN * BATCH];

__device__ __forceinline__ ull fma2(ull a, ull b, ull c) {
    ull d;
    asm("fma.rn.f32x2 %0, %1, %2, %3;" : "=l"(d) : "l"(a), "l"(b), "l"(c));
    return d;
}
__device__ __forceinline__ ull pack2(float lo, float hi) {
    ull d;
    asm("mov.b64 %0, {%1, %2};" : "=l"(d) : "f"(lo), "f"(hi));
    return d;
}
__device__ __forceinline__ void unpack2(ull v, float& lo, float& hi) {
    asm("mov.b64 {%0, %1}, %2;" : "=f"(lo), "=f"(hi) : "l"(v));
}

__device__ __forceinline__ float sigf(float x) {
    return __fdividef(1.0f, 1.0f + __expf(-x));
}
__device__ __forceinline__ float tanhfast(float x) {
    return 2.0f * sigf(2.0f * x) - 1.0f;
}

// cell update on a packed pair of batch lanes; gate order i, j, f, o
__device__ __forceinline__ void cell2(ull zi, ull zj, ull zf, ull zo,
                                      ull& c, float& h0, float& h1)
{
    float i0,i1,j0,j1,f0,f1,o0,o1,c0,c1;
    unpack2(zi,i0,i1); unpack2(zj,j0,j1);
    unpack2(zf,f0,f1); unpack2(zo,o0,o1);
    unpack2(c,c0,c1);
    c0 = sigf(f0 + 1.0f) * c0 + sigf(i0) * tanhfast(j0);
    c1 = sigf(f1 + 1.0f) * c1 + sigf(i1) * tanhfast(j1);
    h0 = sigf(o0) * tanhfast(c0);
    h1 = sigf(o1) * tanhfast(c1);
    c = pack2(c0, c1);
}

// 4-gate x 2-packed-batch tile (4 batch lanes per thread)
template<int KN, int WS>
__device__ __forceinline__ void gemm2(ull (&acc)[4][2],
                                      const ull* __restrict__ wd,
                                      const float* __restrict__ a)
{
    #pragma unroll 5
    for (int k = 0; k < KN; ++k) {
        ulonglong2 w01 = *(const ulonglong2*)(wd);
        ulonglong2 w23 = *(const ulonglong2*)(wd + 2);
        ulonglong2 av  = *(const ulonglong2*)(a);
        wd += WS; a += BTP;
        acc[0][0] = fma2(w01.x, av.x, acc[0][0]);
        acc[0][1] = fma2(w01.x, av.y, acc[0][1]);
        acc[1][0] = fma2(w01.y, av.x, acc[1][0]);
        acc[1][1] = fma2(w01.y, av.y, acc[1][1]);
        acc[2][0] = fma2(w23.x, av.x, acc[2][0]);
        acc[2][1] = fma2(w23.x, av.y, acc[2][1]);
        acc[3][0] = fma2(w23.y, av.x, acc[3][0]);
        acc[3][1] = fma2(w23.y, av.y, acc[3][1]);
    }
}

// 4-gate x 4-packed-batch tile (8 batch lanes per thread)
template<int KN, int WS>
__device__ __forceinline__ void gemm4(ull (&acc)[4][4],
                                      const ull* __restrict__ wd,
                                      const float* __restrict__ a)
{
    #pragma unroll 5
    for (int k = 0; k < KN; ++k) {
        ulonglong2 w01 = *(const ulonglong2*)(wd);
        ulonglong2 w23 = *(const ulonglong2*)(wd + 2);
        ulonglong2 a01 = *(const ulonglong2*)(a);
        ulonglong2 a23 = *(const ulonglong2*)(a + 4);
        wd += WS; a += BTP;
        ull wr[4] = {w01.x, w01.y, w23.x, w23.y};
        ull ar[4] = {a01.x, a01.y, a23.x, a23.y};
        #pragma unroll
        for (int g = 0; g < 4; ++g)
            #pragma unroll
            for (int p = 0; p < 4; ++p)
                acc[g][p] = fma2(wr[g], ar[p], acc[g][p]);
    }
}

// ====================== x transpose: [B][T][D] -> [T][D][B] ======================
#define TT 256
__global__ void __launch_bounds__(TT)
xpose_kernel(const float* __restrict__ x)
{
    __shared__ float s[DIN * 65];
    const int t  = blockIdx.x;          // 0..299
    const int b0 = blockIdx.y * 64;     // batch tile
    const int tid = threadIdx.x;

    for (int i = tid; i < 64 * DIN; i += TT) {
        int b = i / DIN, d = i - b * DIN;
        s[d * 65 + b] = x[((size_t)(b0 + b) * T_STEPS + t) * DIN + d];
    }
    __syncthreads();
    for (int i = tid; i < DIN * 64; i += TT) {
        int d = i >> 6, b = i & 63;
        g_xT[((size_t)t * DIN + d) * BATCH + b0 + b] = s[d * 65 + b];
    }
}

extern __shared__ float smem[];

__global__ void __launch_bounds__(NT)
lstm_kernel(const float* __restrict__ fw_W1, const float* __restrict__ fw_b1,
            const float* __restrict__ fw_W2, const float* __restrict__ fw_b2,
            const float* __restrict__ bw_W1, const float* __restrict__ bw_b1,
            const float* __restrict__ bw_W2, const float* __restrict__ bw_b2)
{
    const int dir = blockIdx.y;
    const int b0  = blockIdx.x * BT;
    const int tid = threadIdx.x;

    float* W1d = smem + OFF_W1D;
    float* W2d = smem + OFF_W2D;
    float* b1p = smem + OFF_B1;
    float* b2p = smem + OFF_B2;
    float* xT  = smem + OFF_X;
    float* h1T = smem + OFF_H1;
    float* h2T = smem + OFF_H2;

    const float* W1g = dir ? bw_W1 : fw_W1;
    const float* b1g = dir ? bw_b1 : fw_b1;
    const float* W2g = dir ? bw_W2 : fw_W2;
    const float* b2g = dir ? bw_b2 : fw_b2;

    // permute (unit-major gate order i,j,f,o) + duplicate weights for f32x2
    for (int i = tid; i < K1*G1P; i += NT) {
        int k = i / G1P, col = i - k * G1P;
        int u = col >> 2, g = col & 3;
        float w = (u < H1D) ? W1g[k*G1 + g*H1D + u] : 0.f;
        W1d[k*2*G1P + 2*col]     = w;
        W1d[k*2*G1P + 2*col + 1] = w;
    }
    for (int i = tid; i < K2*G2P; i += NT) {
        int k = i / G2P, col = i - k * G2P;
        int u = col >> 2, g = col & 3;
        float w = (u < H2D) ? W2g[k*G2 + g*H2D + u] : 0.f;
        W2d[k*2*G2P + 2*col]     = w;
        W2d[k*2*G2P + 2*col + 1] = w;
    }
    for (int i = tid; i < G1P; i += NT) {
        int u = i >> 2, g = i & 3;
        b1p[i] = (u < H1D) ? b1g[g*H1D + u] : 0.f;
    }
    for (int i = tid; i < G2P; i += NT) {
        int u = i >> 2, g = i & 3;
        b2p[i] = (u < H2D) ? b2g[g*H2D + u] : 0.f;
    }
    for (int i = tid; i < H1_BUF; i += NT) { h1T[i] = 0.f; h1T[H1_BUF + i] = 0.f; }
    for (int i = tid; i < H2_BUF; i += NT) { h2T[i] = 0.f; h2T[H2_BUF + i] = 0.f; }

    // stage x for t=0 into x buffer 0 (coalesced from g_xT)
    {
        const int tx0 = dir ? (T_STEPS - 1) : 0;
        for (int i = tid; i < DIN*16; i += NT) {
            int d = i >> 4, r = i & 15;
            *(float4*)(xT + d*BTP + r*4) =
                *(const float4*)(&g_xT[((size_t)tx0*DIN + d)*BATCH + b0 + r*4]);
        }
    }
    __syncthreads();

    ull c1r[2] = {0,0};
    ull c2r[4] = {0,0,0,0};

    // roles (warp-aligned):
    //  tid   0..575 : layer-1, unit = tid>>4 (0..35; 35 dummy), 4 lanes
    //  tid 576..831 : layer-2, unit = (tid-576)>>3 (0..31; 30,31 dummy), 8 lanes
    //  tid 832..863 : x stager warp
    // pipelined ticks: L1 computes h1[tk] (tk<T); L2 computes h2[tk-1] (tk>=1)
    for (int tk = 0; tk <= T_STEPS; ++tk) {
        const int wb = tk & 1, rb = wb ^ 1;

        if (tid < N_L1) {
            if (tk < T_STEPS) {
                const int unit = tid >> 4;
                const int bcol = (tid & 15) * 4;
                const float* xc  = xT  + wb * X_BUF;   // x[tk]
                const float* h1c = h1T + rb * H1_BUF;  // h1[tk-1]
                float*       h1n = h1T + wb * H1_BUF;  // h1[tk]

                ull acc[4][2];
                #pragma unroll
                for (int g = 0; g < 4; ++g) {
                    float bb = b1p[unit*4 + g];
                    ull bp = pack2(bb, bb);
                    acc[g][0] = bp; acc[g][1] = bp;
                }
                const ull* wd = (const ull*)W1d + unit*4;
                gemm2<DIN, G1P>(acc, wd,             xc  + bcol);
                gemm2<H1D, G1P>(acc, wd + DIN*G1P,   h1c + bcol);

                float h[4];
                cell2(acc[0][0], acc[1][0], acc[2][0], acc[3][0], c1r[0], h[0], h[1]);
                cell2(acc[0][1], acc[1][1], acc[2][1], acc[3][1], c1r[1], h[2], h[3]);
                *(float4*)(h1n + unit*BTP + bcol) = make_float4(h[0], h[1], h[2], h[3]);
            }
        } else if (tid < N_L12) {
            if (tk >= 1) {
                const int lt   = tid - N_L1;
                const int unit = lt >> 3;          // 0..31
                const int bcol = (lt & 7) * 8;     // 8 lanes
                const float* h1p = h1T + rb * H1_BUF;  // h1[tk-1]
                const float* h2c = h2T + wb * H2_BUF;  // h2[tk-2]
                float*       h2n = h2T + rb * H2_BUF;  // h2[tk-1]

                ull acc[4][4];
                #pragma unroll
                for (int g = 0; g < 4; ++g) {
                    float bb = b2p[unit*4 + g];
                    ull bp = pack2(bb, bb);
                    #pragma unroll
                    for (int p = 0; p < 4; ++p) acc[g][p] = bp;
                }
                const ull* wd = (const ull*)W2d + unit*4;
                gemm4<H1D, G2P>(acc, wd,             h1p + bcol);
                gemm4<H2D, G2P>(acc, wd + H1D*G2P,   h2c + bcol);

                float h[8];
                #pragma unroll
                for (int p = 0; p < 4; ++p)
                    cell2(acc[0][p], acc[1][p], acc[2][p], acc[3][p],
                          c2r[p], h[2*p], h[2*p+1]);
                float* dst = h2n + unit*BTP + bcol;
                *(float4*)(dst)     = make_float4(h[0], h[1], h[2], h[3]);
                *(float4*)(dst + 4) = make_float4(h[4], h[5], h[6], h[7]);

                if (unit < H2D) {
                    const int tx = dir ? (T_STEPS - tk) : (tk - 1);
                    float* gd = &g_hbuf[((size_t)(tx*60 + dir*H2D + unit))*BATCH + b0 + bcol];
                    *(float4*)(gd)     = make_float4(h[0], h[1], h[2], h[3]);
                    *(float4*)(gd + 4) = make_float4(h[4], h[5], h[6], h[7]);
                }
            }
        } else {
            if (tk + 1 < T_STEPS) {
                // stage x[tk+1] into the other x buffer
                const int txn = dir ? (T_STEPS - 2 - tk) : (tk + 1);
                float* xn = xT + rb * X_BUF;
                #pragma unroll 4
                for (int i = tid - N_L12; i < DIN*16; i += NT - N_L12) {
                    int d = i >> 4, r = i & 15;
                    *(float4*)(xn + d*BTP + r*4) =
                        *(const float4*)(&g_xT[((size_t)txn*DIN + d)*BATCH + b0 + r*4]);
                }
            }
        }
        __syncthreads();
    }
}

// =============================== FC head ===================================
#define FCT 128
#define FOFF_W1 0                       // 60*52 (padded cols 50,51 = 0)
#define FOFF_W2 (FOFF_W1 + 60*52)       // size 2000
#define FOFF_W3 (FOFF_W2 + 50*40)       // size 80
#define FOFF_B1 (FOFF_W3 + 80)          // size 52
#define FOFF_B2 (FOFF_B1 + 52)          // size 40
#define FOFF_B3 (FOFF_B2 + 40)          // size 4
#define FSM_FLOATS (FOFF_B3 + 4)        // 21184 B

__global__ void __launch_bounds__(FCT)
fc_kernel(const float* __restrict__ Wf1, const float* __restrict__ bf1,
          const float* __restrict__ Wf2, const float* __restrict__ bf2,
          const float* __restrict__ Wf3, const float* __restrict__ bf3,
          float* __restrict__ out)
{
    extern __shared__ float fsm[];
    float* W1s = fsm + FOFF_W1;
    float* W2s = fsm + FOFF_W2;
    float* W3s = fsm + FOFF_W3;
    float* B1s = fsm + FOFF_B1;
    float* B2s = fsm + FOFF_B2;
    float* B3s = fsm + FOFF_B3;

    const int tid = threadIdx.x;

    for (int i = tid; i < 60*52; i += FCT) {
        int k = i / 52, j = i - k * 52;
        W1s[i] = (j < 50) ? Wf1[k*50 + j] : 0.f;
    }
    for (int i = tid; i < 50*40; i += FCT) W2s[i] = Wf2[i];
    for (int i = tid; i < 80;    i += FCT) W3s[i] = Wf3[i];
    for (int i = tid; i < 52;    i += FCT) B1s[i] = (i < 50) ? bf1[i] : 0.f;
    for (int i = tid; i < 40;    i += FCT) B2s[i] = bf2[i];
    for (int i = tid; i < 2;     i += FCT) B3s[i] = bf3[i];
    __syncthreads();

    const int bi = blockIdx.x & 31;          // 32 tiles of 128 batch
    const int t  = blockIdx.x >> 5;          // 0..299
    const int b0 = bi * FCT;
    const float* __restrict__ hb = &g_hbuf[(size_t)t * 60 * BATCH + b0 + tid];

    // fc1: 60 -> 50 (padded 52), packed f32x2 accumulators, direct gmem reads
    ull acc1[26];
    #pragma unroll
    for (int j = 0; j < 26; ++j) acc1[j] = pack2(B1s[2*j], B1s[2*j+1]);
    #pragma unroll 4
    for (int k = 0; k < 60; ++k) {
        float v = hb[(size_t)k * BATCH];
        ull vv = pack2(v, v);
        #pragma unroll
        for (int j = 0; j < 13; ++j) {
            ulonglong2 w = *(const ulonglong2*)(W1s + k*52 + j*4);
            acc1[2*j]   = fma2(vv, w.x, acc1[2*j]);
            acc1[2*j+1] = fma2(vv, w.y, acc1[2*j+1]);
        }
    }
    float a1[52];
    #pragma unroll
    for (int j = 0; j < 26; ++j) {
        float lo, hi; unpack2(acc1[j], lo, hi);
        a1[2*j]   = fmaxf(lo, 0.f);
        a1[2*j+1] = fmaxf(hi, 0.f);
    }

    // fc2: 50 -> 40
    ull acc2[20];
    #pragma unroll
    for (int j = 0; j < 20; ++j) acc2[j] = pack2(B2s[2*j], B2s[2*j+1]);
    #pragma unroll 5
    for (int k = 0; k < 50; ++k) {
        ull vv = pack2(a1[k], a1[k]);
        #pragma unroll
        for (int j = 0; j < 10; ++j) {
            ulonglong2 w = *(const ulonglong2*)(W2s + k*40 + j*4);
            acc2[2*j]   = fma2(vv, w.x, acc2[2*j]);
            acc2[2*j+1] = fma2(vv, w.y, acc2[2*j+1]);
        }
    }
    float a2[40];
    #pragma unroll
    for (int j = 0; j < 20; ++j) {
        float lo, hi; unpack2(acc2[j], lo, hi);
        a2[2*j]   = fmaxf(lo, 0.f);
        a2[2*j+1] = fmaxf(hi, 0.f);
    }

    // out: 40 -> 2
    float o0 = B3s[0], o1 = B3s[1];
    #pragma unroll
    for (int k = 0; k < 40; ++k) {
        o0 = fmaf(a2[k], W3s[2*k + 0], o0);
        o1 = fmaf(a2[k], W3s[2*k + 1], o1);
    }
    float2 ov = make_float2(o0, o1);
    *(float2*)(&out[((size_t)(b0 + tid) * T_STEPS + t) * 2]) = ov;
}

// ============================================================================
extern "C" void kernel_launch(void* const* d_in, const int* in_sizes, int n_in,
                              void* d_out, int out_size)
{
    const float* x     = (const float*)d_in[0];
    const float* fw_W1 = (const float*)d_in[1];
    const float* fw_b1 = (const float*)d_in[2];
    const float* fw_W2 = (const float*)d_in[3];
    const float* fw_b2 = (const float*)d_in[4];
    const float* bw_W1 = (const float*)d_in[5];
    const float* bw_b1 = (const float*)d_in[6];
    const float* bw_W2 = (const float*)d_in[7];
    const float* bw_b2 = (const float*)d_in[8];
    const float* Wf1   = (const float*)d_in[9];
    const float* bf1   = (const float*)d_in[10];
    const float* Wf2   = (const float*)d_in[11];
    const float* bf2   = (const float*)d_in[12];
    const float* Wf3   = (const float*)d_in[13];
    const float* bf3   = (const float*)d_in[14];

    cudaFuncSetAttribute(lstm_kernel, cudaFuncAttributeMaxDynamicSharedMemorySize,
                         SM_FLOATS * (int)sizeof(float));
    cudaFuncSetAttribute(fc_kernel, cudaFuncAttributeMaxDynamicSharedMemorySize,
                         FSM_FLOATS * (int)sizeof(float));

    xpose_kernel<<<dim3(T_STEPS, BATCH/64), TT>>>(x);

    lstm_kernel<<<dim3(NBLK, 2), NT, SM_FLOATS * sizeof(float)>>>(
        fw_W1, fw_b1, fw_W2, fw_b2, bw_W1, bw_b1, bw_W2, bw_b2);

    fc_kernel<<<32 * T_STEPS, FCT, FSM_FLOATS * sizeof(float)>>>(
        Wf1, bf1, Wf2, bf2, Wf3, bf3, (float*)d_out);
}

// round 10
// speedup vs baseline: 1.4686x; 1.4686x over previous
#include <cuda_runtime.h>
#include <cuda_bf16.h>
#include <math.h>

#define T_STEPS 300
#define DIN 39
#define H1D 35
#define H2D 30
#define BT 64
#define BATCH 4096
#define NBLK (BATCH/BT)
#define NT 640

#define KP 84            // row stride (bf16 elems) for A and W-nmajor
#define N1 144           // L1 gate cols (36 units * 4)
#define N2 128           // L2 gate cols (32 units * 4)
#define ZP 148           // z row stride (floats)

// smem byte offsets
#define Z_OFF    0
#define B1_OFF   37888
#define B2_OFF   38464
#define W1H_OFF  38976
#define W1L_OFF  63168
#define W2H_OFF  87360
#define W2L_OFF  108864
#define A1H_OFF  130368
#define A1L_OFF  141120
#define A2H_OFF  151872
#define A2L_OFF  162624
#define SMEM_BYTES 173376

typedef unsigned long long ull;
typedef unsigned short u16;
typedef unsigned int u32;

// scratch: LSTM hidden states [T][60][B]  (fw units [0,30), bw [30,60))
__device__ float g_hbuf[(size_t)BATCH * T_STEPS * 60];
// pre-split transposed input, A-operand layout [T][btile][64 rows][40 cols]
__device__ u16 g_xhi[(size_t)T_STEPS * NBLK * 64 * 40];
__device__ u16 g_xlo[(size_t)T_STEPS * NBLK * 64 * 40];

// ---------------- helpers ----------------
__device__ __forceinline__ ull fma2(ull a, ull b, ull c) {
    ull d;
    asm("fma.rn.f32x2 %0, %1, %2, %3;" : "=l"(d) : "l"(a), "l"(b), "l"(c));
    return d;
}
__device__ __forceinline__ ull pack2(float lo, float hi) {
    ull d;
    asm("mov.b64 %0, {%1, %2};" : "=l"(d) : "f"(lo), "f"(hi));
    return d;
}
__device__ __forceinline__ void unpack2(ull v, float& lo, float& hi) {
    asm("mov.b64 {%0, %1}, %2;" : "=f"(lo), "=f"(hi) : "l"(v));
}
__device__ __forceinline__ float sigf(float x) {
    return __fdividef(1.0f, 1.0f + __expf(-x));
}
__device__ __forceinline__ float tanhfast(float x) {
    return 2.0f * sigf(2.0f * x) - 1.0f;
}
__device__ __forceinline__ float cellone(float zi, float zj, float zf, float zo, float& c) {
    c = sigf(zf + 1.0f) * c + sigf(zi) * tanhfast(zj);
    return sigf(zo) * tanhfast(c);
}
__device__ __forceinline__ void bsplit(float v, u16& hi, u16& lo) {
    __nv_bfloat16 h = __float2bfloat16(v);
    float r = v - __bfloat162float(h);
    __nv_bfloat16 l = __float2bfloat16(r);
    hi = __bfloat16_as_ushort(h);
    lo = __bfloat16_as_ushort(l);
}
__device__ __forceinline__ u32 pk16(u16 a, u16 b) { return (u32)a | ((u32)b << 16); }

__device__ __forceinline__ void mma16816(float& c0, float& c1, float& c2, float& c3,
                                         u32 a0, u32 a1, u32 a2, u32 a3,
                                         u32 b0, u32 b1)
{
    asm volatile("mma.sync.aligned.m16n8k16.row.col.f32.bf16.bf16.f32 "
                 "{%0,%1,%2,%3},{%4,%5,%6,%7},{%8,%9},{%0,%1,%2,%3};"
                 : "+f"(c0), "+f"(c1), "+f"(c2), "+f"(c3)
                 : "r"(a0), "r"(a1), "r"(a2), "r"(a3), "r"(b0), "r"(b1));
}

// one warp computes NCNT m16n8 z-tiles: z[m-tile mi][n-tiles n0..n0+NCNT)
// full 4-product bf16 split accumulation, K = 80 (5 chunks of 16)
template<int NCNT>
__device__ __forceinline__ void mma_layer(
    const u16* __restrict__ Ah, const u16* __restrict__ Al,
    const u16* __restrict__ Wh, const u16* __restrict__ Wl,
    float* __restrict__ z, int mi, int n0, int lane)
{
    const int g  = lane >> 2;
    const int t2 = (lane & 3) * 2;
    float acc[NCNT][4];
    #pragma unroll
    for (int i = 0; i < NCNT; ++i) {
        acc[i][0] = 0.f; acc[i][1] = 0.f; acc[i][2] = 0.f; acc[i][3] = 0.f;
    }
    const int ar0 = (mi*16 + g)*KP + t2;
    const int ar1 = ar0 + 8*KP;
    #pragma unroll
    for (int kc = 0; kc < 5; ++kc) {
        const int ka = kc * 16;
        u32 ah0 = *(const u32*)(Ah + ar0 + ka);
        u32 ah1 = *(const u32*)(Ah + ar1 + ka);
        u32 ah2 = *(const u32*)(Ah + ar0 + ka + 8);
        u32 ah3 = *(const u32*)(Ah + ar1 + ka + 8);
        u32 al0 = *(const u32*)(Al + ar0 + ka);
        u32 al1 = *(const u32*)(Al + ar1 + ka);
        u32 al2 = *(const u32*)(Al + ar0 + ka + 8);
        u32 al3 = *(const u32*)(Al + ar1 + ka + 8);
        #pragma unroll
        for (int nt = 0; nt < NCNT; ++nt) {
            const int wr = ((n0 + nt)*8 + g)*KP + t2 + ka;
            u32 bh0 = *(const u32*)(Wh + wr);
            u32 bh1 = *(const u32*)(Wh + wr + 8);
            u32 bl0 = *(const u32*)(Wl + wr);
            u32 bl1 = *(const u32*)(Wl + wr + 8);
            mma16816(acc[nt][0],acc[nt][1],acc[nt][2],acc[nt][3], ah0,ah1,ah2,ah3, bh0,bh1);
            mma16816(acc[nt][0],acc[nt][1],acc[nt][2],acc[nt][3], ah0,ah1,ah2,ah3, bl0,bl1);
            mma16816(acc[nt][0],acc[nt][1],acc[nt][2],acc[nt][3], al0,al1,al2,al3, bh0,bh1);
            mma16816(acc[nt][0],acc[nt][1],acc[nt][2],acc[nt][3], al0,al1,al2,al3, bl0,bl1);
        }
    }
    #pragma unroll
    for (int nt = 0; nt < NCNT; ++nt) {
        float* zr = z + (mi*16 + g)*ZP + (n0 + nt)*8 + t2;
        *(float2*)zr          = make_float2(acc[nt][0], acc[nt][1]);
        *(float2*)(zr + 8*ZP) = make_float2(acc[nt][2], acc[nt][3]);
    }
}

// ============ x prep: [B][T][D] fp32 -> [T][btile][64][40] bf16 hi/lo ============
#define TT 256
__global__ void __launch_bounds__(TT)
xsplit_kernel(const float* __restrict__ x)
{
    __shared__ float s[DIN * 65];
    const int t  = blockIdx.x;
    const int bt = blockIdx.y;
    const int b0 = bt * 64;
    const int tid = threadIdx.x;

    for (int i = tid; i < 64 * DIN; i += TT) {
        int b = i / DIN, d = i - b * DIN;
        s[d * 65 + b] = x[((size_t)(b0 + b) * T_STEPS + t) * DIN + d];
    }
    __syncthreads();
    const size_t base = ((size_t)t * NBLK + bt) * 2560;
    for (int i = tid; i < 2560; i += TT) {
        int b = i / 40, d = i - b * 40;
        float v = (d < DIN) ? s[d * 65 + b] : 0.f;
        u16 hi, lo; bsplit(v, hi, lo);
        g_xhi[base + i] = hi;
        g_xlo[base + i] = lo;
    }
}

// =============================== LSTM kernel ===============================
extern __shared__ char smc[];

__global__ void __launch_bounds__(NT)
lstm_kernel(const float* __restrict__ fw_W1, const float* __restrict__ fw_b1,
            const float* __restrict__ fw_W2, const float* __restrict__ fw_b2,
            const float* __restrict__ bw_W1, const float* __restrict__ bw_b1,
            const float* __restrict__ bw_W2, const float* __restrict__ bw_b2)
{
    const int dir = blockIdx.y;
    const int bti = blockIdx.x;
    const int b0g = bti * BT;
    const int tid = threadIdx.x;

    float* z   = (float*)(smc + Z_OFF);
    float* b1s = (float*)(smc + B1_OFF);
    float* b2s = (float*)(smc + B2_OFF);
    u16* W1h = (u16*)(smc + W1H_OFF);
    u16* W1l = (u16*)(smc + W1L_OFF);
    u16* W2h = (u16*)(smc + W2H_OFF);
    u16* W2l = (u16*)(smc + W2L_OFF);
    u16* A1h = (u16*)(smc + A1H_OFF);
    u16* A1l = (u16*)(smc + A1L_OFF);
    u16* A2h = (u16*)(smc + A2H_OFF);
    u16* A2l = (u16*)(smc + A2L_OFF);

    const float* W1g = dir ? bw_W1 : fw_W1;
    const float* b1g = dir ? bw_b1 : fw_b1;
    const float* W2g = dir ? bw_W2 : fw_W2;
    const float* b2g = dir ? bw_b2 : fw_b2;

    // ---- prologue: zero A, split weights (n-major, unit-major gates), biases ----
    for (int i = tid; i < 64*KP; i += NT) { A1h[i]=0; A1l[i]=0; A2h[i]=0; A2l[i]=0; }

    // A/W column map L1: cols 0..34 = h1 units, 35 pad, 36..74 = x dims, 75.. pad
    for (int i = tid; i < N1*KP; i += NT) {
        int n = i / KP, c = i - n * KP;
        int u = n >> 2, gg = n & 3;
        float v = 0.f;
        if (u < H1D) {
            int col = gg*H1D + u;
            int kr = -1;
            if (c < H1D) kr = 39 + c;
            else if (c >= 36 && c < 36 + DIN) kr = c - 36;
            if (kr >= 0) v = W1g[kr*140 + col];
        }
        u16 hi, lo; bsplit(v, hi, lo);
        W1h[i] = hi; W1l[i] = lo;
    }
    // L2: cols 0..34 = h1 units, 35 pad, 36..65 = h2 units, 66.. pad
    for (int i = tid; i < N2*KP; i += NT) {
        int n = i / KP, c = i - n * KP;
        int u = n >> 2, gg = n & 3;
        float v = 0.f;
        if (u < H2D) {
            int col = gg*H2D + u;
            int kr = -1;
            if (c < H1D) kr = c;
            else if (c >= 36 && c < 36 + H2D) kr = H1D + (c - 36);
            if (kr >= 0) v = W2g[kr*120 + col];
        }
        u16 hi, lo; bsplit(v, hi, lo);
        W2h[i] = hi; W2l[i] = lo;
    }
    for (int i = tid; i < N1; i += NT) {
        int u = i >> 2, gg = i & 3;
        b1s[i] = (u < H1D) ? b1g[gg*H1D + u] : 0.f;
    }
    for (int i = tid; i < N2; i += NT) {
        int u = i >> 2, gg = i & 3;
        b2s[i] = (u < H2D) ? b2g[gg*H2D + u] : 0.f;
    }
    // stage x_0
    {
        const int tx0 = dir ? (T_STEPS - 1) : 0;
        const size_t base = ((size_t)tx0 * NBLK + bti) * 2560;
        for (int i = tid; i < 2560; i += NT) {
            int r = i / 40, d = i - r * 40;
            A1h[r*KP + 36 + d] = g_xhi[base + i];
            A1l[r*KP + 36 + d] = g_xlo[base + i];
        }
    }
    __syncthreads();

    float c1s[4] = {0.f, 0.f, 0.f, 0.f};
    float c2s[4] = {0.f, 0.f, 0.f, 0.f};

    const int warp = tid >> 5, lane = tid & 31;
    const int mi = warp & 3, ngp = warp >> 2;

    for (int tk = 0; tk < T_STEPS; ++tk) {
        const int tx = dir ? (T_STEPS - 1 - tk) : tk;

        // ---- P1: MMA layer 1 -> z[64][144] ----
        if (tid < 512) {
            if (ngp == 0)      mma_layer<5>(A1h, A1l, W1h, W1l, z, mi, 0,  lane);
            else if (ngp == 1) mma_layer<5>(A1h, A1l, W1h, W1l, z, mi, 5,  lane);
            else if (ngp == 2) mma_layer<4>(A1h, A1l, W1h, W1l, z, mi, 10, lane);
            else               mma_layer<4>(A1h, A1l, W1h, W1l, z, mi, 14, lane);
        }
        __syncthreads();

        // ---- P2: cell layer 1 (576 threads: 64 batch x 9 unit-groups) ----
        if (tid < 576) {
            const int b = tid & 63, ug = tid >> 6;
            const float* zr = z + b*ZP + ug*16;
            const float4 q0 = *(const float4*)(zr);
            const float4 q1 = *(const float4*)(zr + 4);
            const float4 q2 = *(const float4*)(zr + 8);
            const float4 q3 = *(const float4*)(zr + 12);
            const float* bb = b1s + ug*16;
            float h0 = cellone(q0.x+bb[0],  q0.y+bb[1],  q0.z+bb[2],  q0.w+bb[3],  c1s[0]);
            float h1 = cellone(q1.x+bb[4],  q1.y+bb[5],  q1.z+bb[6],  q1.w+bb[7],  c1s[1]);
            float h2 = cellone(q2.x+bb[8],  q2.y+bb[9],  q2.z+bb[10], q2.w+bb[11], c1s[2]);
            float h3 = cellone(q3.x+bb[12], q3.y+bb[13], q3.z+bb[14], q3.w+bb[15], c1s[3]);
            u16 hh0,hl0,hh1,hl1,hh2,hl2,hh3,hl3;
            bsplit(h0,hh0,hl0); bsplit(h1,hh1,hl1);
            bsplit(h2,hh2,hl2); bsplit(h3,hh3,hl3);
            uint2 ph = make_uint2(pk16(hh0,hh1), pk16(hh2,hh3));
            uint2 pl = make_uint2(pk16(hl0,hl1), pk16(hl2,hl3));
            const int off = b*KP + ug*4;   // h1 cols 0..35 in both A1 and A2
            *(uint2*)(A1h + off) = ph;
            *(uint2*)(A1l + off) = pl;
            *(uint2*)(A2h + off) = ph;
            *(uint2*)(A2l + off) = pl;
        }
        __syncthreads();

        // ---- P3: MMA layer 2 -> z[64][128]; warps 16-19 stage x[tk+1] ----
        if (tid < 512) {
            mma_layer<4>(A2h, A2l, W2h, W2l, z, mi, ngp*4, lane);
        } else if (tk + 1 < T_STEPS) {
            const int txn = dir ? (T_STEPS - 2 - tk) : (tk + 1);
            const size_t base = ((size_t)txn * NBLK + bti) * 2560;
            const int s = tid - 512;            // 0..127
            const int r = s & 63, which = s >> 6;
            const u32* src = (const u32*)((which ? g_xlo : g_xhi) + base + r*40);
            u32* dst = (u32*)((which ? A1l : A1h) + r*KP + 36);
            #pragma unroll
            for (int j = 0; j < 20; ++j) dst[j] = src[j];
        }
        __syncthreads();

        // ---- P4: cell layer 2 (512 threads: 64 batch x 8 unit-groups) ----
        if (tid < 512) {
            const int b = tid & 63, ug = tid >> 6;
            const float* zr = z + b*ZP + ug*16;
            const float4 q0 = *(const float4*)(zr);
            const float4 q1 = *(const float4*)(zr + 4);
            const float4 q2 = *(const float4*)(zr + 8);
            const float4 q3 = *(const float4*)(zr + 12);
            const float* bb = b2s + ug*16;
            float hv[4];
            hv[0] = cellone(q0.x+bb[0],  q0.y+bb[1],  q0.z+bb[2],  q0.w+bb[3],  c2s[0]);
            hv[1] = cellone(q1.x+bb[4],  q1.y+bb[5],  q1.z+bb[6],  q1.w+bb[7],  c2s[1]);
            hv[2] = cellone(q2.x+bb[8],  q2.y+bb[9],  q2.z+bb[10], q2.w+bb[11], c2s[2]);
            hv[3] = cellone(q3.x+bb[12], q3.y+bb[13], q3.z+bb[14], q3.w+bb[15], c2s[3]);
            u16 hh0,hl0,hh1,hl1,hh2,hl2,hh3,hl3;
            bsplit(hv[0],hh0,hl0); bsplit(hv[1],hh1,hl1);
            bsplit(hv[2],hh2,hl2); bsplit(hv[3],hh3,hl3);
            uint2 ph = make_uint2(pk16(hh0,hh1), pk16(hh2,hh3));
            uint2 pl = make_uint2(pk16(hl0,hl1), pk16(hl2,hl3));
            const int off = b*KP + 36 + ug*4;   // h2 cols 36..67 in A2
            *(uint2*)(A2h + off) = ph;
            *(uint2*)(A2l + off) = pl;
            const int ub = ug * 4;
            #pragma unroll
            for (int l = 0; l < 4; ++l) {
                if (ub + l < H2D)
                    g_hbuf[((size_t)(tx*60 + dir*H2D + ub + l))*BATCH + b0g + b] = hv[l];
            }
        }
        __syncthreads();
    }
}

// =============================== FC head (unchanged, passing) ===============================
#define FCT 128
#define FOFF_W1 0
#define FOFF_W2 (FOFF_W1 + 60*52)
#define FOFF_W3 (FOFF_W2 + 50*40)
#define FOFF_B1 (FOFF_W3 + 80)
#define FOFF_B2 (FOFF_B1 + 52)
#define FOFF_B3 (FOFF_B2 + 40)
#define FSM_FLOATS (FOFF_B3 + 4)

__global__ void __launch_bounds__(FCT)
fc_kernel(const float* __restrict__ Wf1, const float* __restrict__ bf1,
          const float* __restrict__ Wf2, const float* __restrict__ bf2,
          const float* __restrict__ Wf3, const float* __restrict__ bf3,
          float* __restrict__ out)
{
    extern __shared__ float fsm[];
    float* W1s = fsm + FOFF_W1;
    float* W2s = fsm + FOFF_W2;
    float* W3s = fsm + FOFF_W3;
    float* B1s = fsm + FOFF_B1;
    float* B2s = fsm + FOFF_B2;
    float* B3s = fsm + FOFF_B3;

    const int tid = threadIdx.x;

    for (int i = tid; i < 60*52; i += FCT) {
        int k = i / 52, j = i - k * 52;
        W1s[i] = (j < 50) ? Wf1[k*50 + j] : 0.f;
    }
    for (int i = tid; i < 50*40; i += FCT) W2s[i] = Wf2[i];
    for (int i = tid; i < 80;    i += FCT) W3s[i] = Wf3[i];
    for (int i = tid; i < 52;    i += FCT) B1s[i] = (i < 50) ? bf1[i] : 0.f;
    for (int i = tid; i < 40;    i += FCT) B2s[i] = bf2[i];
    for (int i = tid; i < 2;     i += FCT) B3s[i] = bf3[i];
    __syncthreads();

    const int bi = blockIdx.x & 31;
    const int t  = blockIdx.x >> 5;
    const int b0 = bi * FCT;
    const float* __restrict__ hb = &g_hbuf[(size_t)t * 60 * BATCH + b0 + tid];

    ull acc1[26];
    #pragma unroll
    for (int j = 0; j < 26; ++j) acc1[j] = pack2(B1s[2*j], B1s[2*j+1]);
    #pragma unroll 4
    for (int k = 0; k < 60; ++k) {
        float v = hb[(size_t)k * BATCH];
        ull vv = pack2(v, v);
        #pragma unroll
        for (int j = 0; j < 13; ++j) {
            ulonglong2 w = *(const ulonglong2*)(W1s + k*52 + j*4);
            acc1[2*j]   = fma2(vv, w.x, acc1[2*j]);
            acc1[2*j+1] = fma2(vv, w.y, acc1[2*j+1]);
        }
    }
    float a1[52];
    #pragma unroll
    for (int j = 0; j < 26; ++j) {
        float lo, hi; unpack2(acc1[j], lo, hi);
        a1[2*j]   = fmaxf(lo, 0.f);
        a1[2*j+1] = fmaxf(hi, 0.f);
    }

    ull acc2[20];
    #pragma unroll
    for (int j = 0; j < 20; ++j) acc2[j] = pack2(B2s[2*j], B2s[2*j+1]);
    #pragma unroll 5
    for (int k = 0; k < 50; ++k) {
        ull vv = pack2(a1[k], a1[k]);
        #pragma unroll
        for (int j = 0; j < 10; ++j) {
            ulonglong2 w = *(const ulonglong2*)(W2s + k*40 + j*4);
            acc2[2*j]   = fma2(vv, w.x, acc2[2*j]);
            acc2[2*j+1] = fma2(vv, w.y, acc2[2*j+1]);
        }
    }
    float a2[40];
    #pragma unroll
    for (int j = 0; j < 20; ++j) {
        float lo, hi; unpack2(acc2[j], lo, hi);
        a2[2*j]   = fmaxf(lo, 0.f);
        a2[2*j+1] = fmaxf(hi, 0.f);
    }

    float o0 = B3s[0], o1 = B3s[1];
    #pragma unroll
    for (int k = 0; k < 40; ++k) {
        o0 = fmaf(a2[k], W3s[2*k + 0], o0);
        o1 = fmaf(a2[k], W3s[2*k + 1], o1);
    }
    float2 ov = make_float2(o0, o1);
    *(float2*)(&out[((size_t)(b0 + tid) * T_STEPS + t) * 2]) = ov;
}

// ============================================================================
extern "C" void kernel_launch(void* const* d_in, const int* in_sizes, int n_in,
                              void* d_out, int out_size)
{
    const float* x     = (const float*)d_in[0];
    const float* fw_W1 = (const float*)d_in[1];
    const float* fw_b1 = (const float*)d_in[2];
    const float* fw_W2 = (const float*)d_in[3];
    const float* fw_b2 = (const float*)d_in[4];
    const float* bw_W1 = (const float*)d_in[5];
    const float* bw_b1 = (const float*)d_in[6];
    const float* bw_W2 = (const float*)d_in[7];
    const float* bw_b2 = (const float*)d_in[8];
    const float* Wf1   = (const float*)d_in[9];
    const float* bf1   = (const float*)d_in[10];
    const float* Wf2   = (const float*)d_in[11];
    const float* bf2   = (const float*)d_in[12];
    const float* Wf3   = (const float*)d_in[13];
    const float* bf3   = (const float*)d_in[14];

    cudaFuncSetAttribute(lstm_kernel, cudaFuncAttributeMaxDynamicSharedMemorySize,
                         SMEM_BYTES);
    cudaFuncSetAttribute(fc_kernel, cudaFuncAttributeMaxDynamicSharedMemorySize,
                         FSM_FLOATS * (int)sizeof(float));

    xsplit_kernel<<<dim3(T_STEPS, NBLK), TT>>>(x);

    lstm_kernel<<<dim3(NBLK, 2), NT, SMEM_BYTES>>>(
        fw_W1, fw_b1, fw_W2, fw_b2, bw_W1, bw_b1, bw_W2, bw_b2);

    fc_kernel<<<32 * T_STEPS, FCT, FSM_FLOATS * sizeof(float)>>>(
        Wf1, bf1, Wf2, bf2, Wf3, bf3, (float*)d_out);
}

// round 11
// speedup vs baseline: 1.4782x; 1.0066x over previous
#include <cuda_runtime.h>
#include <cuda_bf16.h>
#include <math.h>

#define T_STEPS 300
#define DIN 39
#define H1D 35
#define H2D 30
#define BT 64
#define BATCH 4096
#define NBLK (BATCH/BT)
#define NT 640

#define KP 84            // row stride (bf16 elems) for A and W-nmajor
#define N1 144           // L1 gate cols (36 units * 4)
#define N2 128           // L2 gate cols (32 units * 4)
#define ZP 148           // z row stride (floats)

// smem byte offsets
#define Z_OFF    0
#define B1_OFF   37888
#define B2_OFF   38464
#define W1H_OFF  38976
#define W1L_OFF  63168
#define W2H_OFF  87360
#define W2L_OFF  108864
#define A1H_OFF  130368
#define A1L_OFF  141120
#define A2H_OFF  151872
#define A2L_OFF  162624
#define SMEM_BYTES 173376

typedef unsigned long long ull;
typedef unsigned short u16;
typedef unsigned int u32;

// scratch: LSTM hidden states [T][60][B]  (fw units [0,30), bw [30,60))
__device__ float g_hbuf[(size_t)BATCH * T_STEPS * 60];
// pre-split transposed input, A-operand layout [T][btile][64 rows][40 cols]
__device__ u16 g_xhi[(size_t)T_STEPS * NBLK * 64 * 40];
__device__ u16 g_xlo[(size_t)T_STEPS * NBLK * 64 * 40];

// ---------------- helpers ----------------
__device__ __forceinline__ ull fma2(ull a, ull b, ull c) {
    ull d;
    asm("fma.rn.f32x2 %0, %1, %2, %3;" : "=l"(d) : "l"(a), "l"(b), "l"(c));
    return d;
}
__device__ __forceinline__ ull pack2(float lo, float hi) {
    ull d;
    asm("mov.b64 %0, {%1, %2};" : "=l"(d) : "f"(lo), "f"(hi));
    return d;
}
__device__ __forceinline__ void unpack2(ull v, float& lo, float& hi) {
    asm("mov.b64 {%0, %1}, %2;" : "=f"(lo), "=f"(hi) : "l"(v));
}
__device__ __forceinline__ float sigf(float x) {
    return __fdividef(1.0f, 1.0f + __expf(-x));
}
__device__ __forceinline__ float tanhfast(float x) {
    return 2.0f * sigf(2.0f * x) - 1.0f;
}
__device__ __forceinline__ float cellone(float zi, float zj, float zf, float zo, float& c) {
    c = sigf(zf + 1.0f) * c + sigf(zi) * tanhfast(zj);
    return sigf(zo) * tanhfast(c);
}
__device__ __forceinline__ void bsplit(float v, u16& hi, u16& lo) {
    __nv_bfloat16 h = __float2bfloat16(v);
    float r = v - __bfloat162float(h);
    __nv_bfloat16 l = __float2bfloat16(r);
    hi = __bfloat16_as_ushort(h);
    lo = __bfloat16_as_ushort(l);
}
__device__ __forceinline__ u32 pk16(u16 a, u16 b) { return (u32)a | ((u32)b << 16); }

__device__ __forceinline__ void mma16816(float& c0, float& c1, float& c2, float& c3,
                                         u32 a0, u32 a1, u32 a2, u32 a3,
                                         u32 b0, u32 b1)
{
    asm volatile("mma.sync.aligned.m16n8k16.row.col.f32.bf16.bf16.f32 "
                 "{%0,%1,%2,%3},{%4,%5,%6,%7},{%8,%9},{%0,%1,%2,%3};"
                 : "+f"(c0), "+f"(c1), "+f"(c2), "+f"(c3)
                 : "r"(a0), "r"(a1), "r"(a2), "r"(a3), "r"(b0), "r"(b1));
}

// one warp computes NCNT m16n8 z-tiles: z[m-tile mi][n-tiles n0..n0+NCNT)
// 3-product bf16 split (hi*hi + hi*lo + lo*hi; lo*lo ~2^-18 rel, dropped)
// K = 80 (5 chunks of 16)
template<int NCNT>
__device__ __forceinline__ void mma_layer(
    const u16* __restrict__ Ah, const u16* __restrict__ Al,
    const u16* __restrict__ Wh, const u16* __restrict__ Wl,
    float* __restrict__ z, int mi, int n0, int lane)
{
    const int g  = lane >> 2;
    const int t2 = (lane & 3) * 2;
    float acc[NCNT][4];
    #pragma unroll
    for (int i = 0; i < NCNT; ++i) {
        acc[i][0] = 0.f; acc[i][1] = 0.f; acc[i][2] = 0.f; acc[i][3] = 0.f;
    }
    const int ar0 = (mi*16 + g)*KP + t2;
    const int ar1 = ar0 + 8*KP;
    #pragma unroll
    for (int kc = 0; kc < 5; ++kc) {
        const int ka = kc * 16;
        u32 ah0 = *(const u32*)(Ah + ar0 + ka);
        u32 ah1 = *(const u32*)(Ah + ar1 + ka);
        u32 ah2 = *(const u32*)(Ah + ar0 + ka + 8);
        u32 ah3 = *(const u32*)(Ah + ar1 + ka + 8);
        u32 al0 = *(const u32*)(Al + ar0 + ka);
        u32 al1 = *(const u32*)(Al + ar1 + ka);
        u32 al2 = *(const u32*)(Al + ar0 + ka + 8);
        u32 al3 = *(const u32*)(Al + ar1 + ka + 8);
        #pragma unroll
        for (int nt = 0; nt < NCNT; ++nt) {
            const int wr = ((n0 + nt)*8 + g)*KP + t2 + ka;
            u32 bh0 = *(const u32*)(Wh + wr);
            u32 bh1 = *(const u32*)(Wh + wr + 8);
            u32 bl0 = *(const u32*)(Wl + wr);
            u32 bl1 = *(const u32*)(Wl + wr + 8);
            mma16816(acc[nt][0],acc[nt][1],acc[nt][2],acc[nt][3], ah0,ah1,ah2,ah3, bh0,bh1);
            mma16816(acc[nt][0],acc[nt][1],acc[nt][2],acc[nt][3], ah0,ah1,ah2,ah3, bl0,bl1);
            mma16816(acc[nt][0],acc[nt][1],acc[nt][2],acc[nt][3], al0,al1,al2,al3, bh0,bh1);
        }
    }
    #pragma unroll
    for (int nt = 0; nt < NCNT; ++nt) {
        float* zr = z + (mi*16 + g)*ZP + (n0 + nt)*8 + t2;
        *(float2*)zr          = make_float2(acc[nt][0], acc[nt][1]);
        *(float2*)(zr + 8*ZP) = make_float2(acc[nt][2], acc[nt][3]);
    }
}

// ============ x prep: [B][T][D] fp32 -> [T][btile][64][40] bf16 hi/lo ============
#define TT 256
__global__ void __launch_bounds__(TT)
xsplit_kernel(const float* __restrict__ x)
{
    __shared__ float s[DIN * 65];
    const int t  = blockIdx.x;
    const int bt = blockIdx.y;
    const int b0 = bt * 64;
    const int tid = threadIdx.x;

    for (int i = tid; i < 64 * DIN; i += TT) {
        int b = i / DIN, d = i - b * DIN;
        s[d * 65 + b] = x[((size_t)(b0 + b) * T_STEPS + t) * DIN + d];
    }
    __syncthreads();
    const size_t base = ((size_t)t * NBLK + bt) * 2560;
    for (int i = tid; i < 2560; i += TT) {
        int b = i / 40, d = i - b * 40;
        float v = (d < DIN) ? s[d * 65 + b] : 0.f;
        u16 hi, lo; bsplit(v, hi, lo);
        g_xhi[base + i] = hi;
        g_xlo[base + i] = lo;
    }
}

// =============================== LSTM kernel ===============================
extern __shared__ char smc[];

__global__ void __launch_bounds__(NT)
lstm_kernel(const float* __restrict__ fw_W1, const float* __restrict__ fw_b1,
            const float* __restrict__ fw_W2, const float* __restrict__ fw_b2,
            const float* __restrict__ bw_W1, const float* __restrict__ bw_b1,
            const float* __restrict__ bw_W2, const float* __restrict__ bw_b2)
{
    const int dir = blockIdx.y;
    const int bti = blockIdx.x;
    const int b0g = bti * BT;
    const int tid = threadIdx.x;

    float* z   = (float*)(smc + Z_OFF);
    float* b1s = (float*)(smc + B1_OFF);
    float* b2s = (float*)(smc + B2_OFF);
    u16* W1h = (u16*)(smc + W1H_OFF);
    u16* W1l = (u16*)(smc + W1L_OFF);
    u16* W2h = (u16*)(smc + W2H_OFF);
    u16* W2l = (u16*)(smc + W2L_OFF);
    u16* A1h = (u16*)(smc + A1H_OFF);
    u16* A1l = (u16*)(smc + A1L_OFF);
    u16* A2h = (u16*)(smc + A2H_OFF);
    u16* A2l = (u16*)(smc + A2L_OFF);

    const float* W1g = dir ? bw_W1 : fw_W1;
    const float* b1g = dir ? bw_b1 : fw_b1;
    const float* W2g = dir ? bw_W2 : fw_W2;
    const float* b2g = dir ? bw_b2 : fw_b2;

    // ---- prologue: zero A, split weights (n-major, unit-major gates), biases ----
    for (int i = tid; i < 64*KP; i += NT) { A1h[i]=0; A1l[i]=0; A2h[i]=0; A2l[i]=0; }

    // A/W column map L1: cols 0..34 = h1 units, 35 pad, 36..74 = x dims, 75.. pad
    for (int i = tid; i < N1*KP; i += NT) {
        int n = i / KP, c = i - n * KP;
        int u = n >> 2, gg = n & 3;
        float v = 0.f;
        if (u < H1D) {
            int col = gg*H1D + u;
            int kr = -1;
            if (c < H1D) kr = 39 + c;
            else if (c >= 36 && c < 36 + DIN) kr = c - 36;
            if (kr >= 0) v = W1g[kr*140 + col];
        }
        u16 hi, lo; bsplit(v, hi, lo);
        W1h[i] = hi; W1l[i] = lo;
    }
    // L2: cols 0..34 = h1 units, 35 pad, 36..65 = h2 units, 66.. pad
    for (int i = tid; i < N2*KP; i += NT) {
        int n = i / KP, c = i - n * KP;
        int u = n >> 2, gg = n & 3;
        float v = 0.f;
        if (u < H2D) {
            int col = gg*H2D + u;
            int kr = -1;
            if (c < H1D) kr = c;
            else if (c >= 36 && c < 36 + H2D) kr = H1D + (c - 36);
            if (kr >= 0) v = W2g[kr*120 + col];
        }
        u16 hi, lo; bsplit(v, hi, lo);
        W2h[i] = hi; W2l[i] = lo;
    }
    for (int i = tid; i < N1; i += NT) {
        int u = i >> 2, gg = i & 3;
        b1s[i] = (u < H1D) ? b1g[gg*H1D + u] : 0.f;
    }
    for (int i = tid; i < N2; i += NT) {
        int u = i >> 2, gg = i & 3;
        b2s[i] = (u < H2D) ? b2g[gg*H2D + u] : 0.f;
    }
    // stage x_0
    {
        const int tx0 = dir ? (T_STEPS - 1) : 0;
        const size_t base = ((size_t)tx0 * NBLK + bti) * 2560;
        for (int i = tid; i < 2560; i += NT) {
            int r = i / 40, d = i - r * 40;
            A1h[r*KP + 36 + d] = g_xhi[base + i];
            A1l[r*KP + 36 + d] = g_xlo[base + i];
        }
    }
    __syncthreads();

    float c1s[4] = {0.f, 0.f, 0.f, 0.f};
    float c2s[4] = {0.f, 0.f, 0.f, 0.f};

    const int warp = tid >> 5, lane = tid & 31;
    const int mi = warp & 3, ngp = warp >> 2;

    for (int tk = 0; tk < T_STEPS; ++tk) {
        const int tx = dir ? (T_STEPS - 1 - tk) : tk;

        // ---- P1: MMA layer 1 -> z[64][144] ----
        if (tid < 512) {
            if (ngp == 0)      mma_layer<5>(A1h, A1l, W1h, W1l, z, mi, 0,  lane);
            else if (ngp == 1) mma_layer<5>(A1h, A1l, W1h, W1l, z, mi, 5,  lane);
            else if (ngp == 2) mma_layer<4>(A1h, A1l, W1h, W1l, z, mi, 10, lane);
            else               mma_layer<4>(A1h, A1l, W1h, W1l, z, mi, 14, lane);
        }
        __syncthreads();

        // ---- P2: cell layer 1 (576 threads: 64 batch x 9 unit-groups) ----
        if (tid < 576) {
            const int b = tid & 63, ug = tid >> 6;
            const float* zr = z + b*ZP + ug*16;
            const float4 q0 = *(const float4*)(zr);
            const float4 q1 = *(const float4*)(zr + 4);
            const float4 q2 = *(const float4*)(zr + 8);
            const float4 q3 = *(const float4*)(zr + 12);
            const float* bb = b1s + ug*16;
            float h0 = cellone(q0.x+bb[0],  q0.y+bb[1],  q0.z+bb[2],  q0.w+bb[3],  c1s[0]);
            float h1 = cellone(q1.x+bb[4],  q1.y+bb[5],  q1.z+bb[6],  q1.w+bb[7],  c1s[1]);
            float h2 = cellone(q2.x+bb[8],  q2.y+bb[9],  q2.z+bb[10], q2.w+bb[11], c1s[2]);
            float h3 = cellone(q3.x+bb[12], q3.y+bb[13], q3.z+bb[14], q3.w+bb[15], c1s[3]);
            u16 hh0,hl0,hh1,hl1,hh2,hl2,hh3,hl3;
            bsplit(h0,hh0,hl0); bsplit(h1,hh1,hl1);
            bsplit(h2,hh2,hl2); bsplit(h3,hh3,hl3);
            uint2 ph = make_uint2(pk16(hh0,hh1), pk16(hh2,hh3));
            uint2 pl = make_uint2(pk16(hl0,hl1), pk16(hl2,hl3));
            const int off = b*KP + ug*4;   // h1 cols 0..35 in both A1 and A2
            *(uint2*)(A1h + off) = ph;
            *(uint2*)(A1l + off) = pl;
            *(uint2*)(A2h + off) = ph;
            *(uint2*)(A2l + off) = pl;
        }
        __syncthreads();

        // ---- P3: MMA layer 2 -> z[64][128]; warps 16-19 stage x[tk+1] ----
        if (tid < 512) {
            mma_layer<4>(A2h, A2l, W2h, W2l, z, mi, ngp*4, lane);
        } else if (tk + 1 < T_STEPS) {
            const int txn = dir ? (T_STEPS - 2 - tk) : (tk + 1);
            const size_t base = ((size_t)txn * NBLK + bti) * 2560;
            const int s = tid - 512;            // 0..127
            const int r = s & 63, which = s >> 6;
            const u32* src = (const u32*)((which ? g_xlo : g_xhi) + base + r*40);
            u32* dst = (u32*)((which ? A1l : A1h) + r*KP + 36);
            #pragma unroll
            for (int j = 0; j < 20; ++j) dst[j] = src[j];
        }
        __syncthreads();

        // ---- P4: cell layer 2 (512 threads: 64 batch x 8 unit-groups) ----
        if (tid < 512) {
            const int b = tid & 63, ug = tid >> 6;
            const float* zr = z + b*ZP + ug*16;
            const float4 q0 = *(const float4*)(zr);
            const float4 q1 = *(const float4*)(zr + 4);
            const float4 q2 = *(const float4*)(zr + 8);
            const float4 q3 = *(const float4*)(zr + 12);
            const float* bb = b2s + ug*16;
            float hv[4];
            hv[0] = cellone(q0.x+bb[0],  q0.y+bb[1],  q0.z+bb[2],  q0.w+bb[3],  c2s[0]);
            hv[1] = cellone(q1.x+bb[4],  q1.y+bb[5],  q1.z+bb[6],  q1.w+bb[7],  c2s[1]);
            hv[2] = cellone(q2.x+bb[8],  q2.y+bb[9],  q2.z+bb[10], q2.w+bb[11], c2s[2]);
            hv[3] = cellone(q3.x+bb[12], q3.y+bb[13], q3.z+bb[14], q3.w+bb[15], c2s[3]);
            u16 hh0,hl0,hh1,hl1,hh2,hl2,hh3,hl3;
            bsplit(hv[0],hh0,hl0); bsplit(hv[1],hh1,hl1);
            bsplit(hv[2],hh2,hl2); bsplit(hv[3],hh3,hl3);
            uint2 ph = make_uint2(pk16(hh0,hh1), pk16(hh2,hh3));
            uint2 pl = make_uint2(pk16(hl0,hl1), pk16(hl2,hl3));
            const int off = b*KP + 36 + ug*4;   // h2 cols 36..67 in A2
            *(uint2*)(A2h + off) = ph;
            *(uint2*)(A2l + off) = pl;
            const int ub = ug * 4;
            #pragma unroll
            for (int l = 0; l < 4; ++l) {
                if (ub + l < H2D)
                    g_hbuf[((size_t)(tx*60 + dir*H2D + ub + l))*BATCH + b0g + b] = hv[l];
            }
        }
        __syncthreads();
    }
}

// =============================== FC head (unchanged, passing) ===============================
#define FCT 128
#define FOFF_W1 0
#define FOFF_W2 (FOFF_W1 + 60*52)
#define FOFF_W3 (FOFF_W2 + 50*40)
#define FOFF_B1 (FOFF_W3 + 80)
#define FOFF_B2 (FOFF_B1 + 52)
#define FOFF_B3 (FOFF_B2 + 40)
#define FSM_FLOATS (FOFF_B3 + 4)

__global__ void __launch_bounds__(FCT)
fc_kernel(const float* __restrict__ Wf1, const float* __restrict__ bf1,
          const float* __restrict__ Wf2, const float* __restrict__ bf2,
          const float* __restrict__ Wf3, const float* __restrict__ bf3,
          float* __restrict__ out)
{
    extern __shared__ float fsm[];
    float* W1s = fsm + FOFF_W1;
    float* W2s = fsm + FOFF_W2;
    float* W3s = fsm + FOFF_W3;
    float* B1s = fsm + FOFF_B1;
    float* B2s = fsm + FOFF_B2;
    float* B3s = fsm + FOFF_B3;

    const int tid = threadIdx.x;

    for (int i = tid; i < 60*52; i += FCT) {
        int k = i / 52, j = i - k * 52;
        W1s[i] = (j < 50) ? Wf1[k*50 + j] : 0.f;
    }
    for (int i = tid; i < 50*40; i += FCT) W2s[i] = Wf2[i];
    for (int i = tid; i < 80;    i += FCT) W3s[i] = Wf3[i];
    for (int i = tid; i < 52;    i += FCT) B1s[i] = (i < 50) ? bf1[i] : 0.f;
    for (int i = tid; i < 40;    i += FCT) B2s[i] = bf2[i];
    for (int i = tid; i < 2;     i += FCT) B3s[i] = bf3[i];
    __syncthreads();

    const int bi = blockIdx.x & 31;
    const int t  = blockIdx.x >> 5;
    const int b0 = bi * FCT;
    const float* __restrict__ hb = &g_hbuf[(size_t)t * 60 * BATCH + b0 + tid];

    ull acc1[26];
    #pragma unroll
    for (int j = 0; j < 26; ++j) acc1[j] = pack2(B1s[2*j], B1s[2*j+1]);
    #pragma unroll 4
    for (int k = 0; k < 60; ++k) {
        float v = hb[(size_t)k * BATCH];
        ull vv = pack2(v, v);
        #pragma unroll
        for (int j = 0; j < 13; ++j) {
            ulonglong2 w = *(const ulonglong2*)(W1s + k*52 + j*4);
            acc1[2*j]   = fma2(vv, w.x, acc1[2*j]);
            acc1[2*j+1] = fma2(vv, w.y, acc1[2*j+1]);
        }
    }
    float a1[52];
    #pragma unroll
    for (int j = 0; j < 26; ++j) {
        float lo, hi; unpack2(acc1[j], lo, hi);
        a1[2*j]   = fmaxf(lo, 0.f);
        a1[2*j+1] = fmaxf(hi, 0.f);
    }

    ull acc2[20];
    #pragma unroll
    for (int j = 0; j < 20; ++j) acc2[j] = pack2(B2s[2*j], B2s[2*j+1]);
    #pragma unroll 5
    for (int k = 0; k < 50; ++k) {
        ull vv = pack2(a1[k], a1[k]);
        #pragma unroll
        for (int j = 0; j < 10; ++j) {
            ulonglong2 w = *(const ulonglong2*)(W2s + k*40 + j*4);
            acc2[2*j]   = fma2(vv, w.x, acc2[2*j]);
            acc2[2*j+1] = fma2(vv, w.y, acc2[2*j+1]);
        }
    }
    float a2[40];
    #pragma unroll
    for (int j = 0; j < 20; ++j) {
        float lo, hi; unpack2(acc2[j], lo, hi);
        a2[2*j]   = fmaxf(lo, 0.f);
        a2[2*j+1] = fmaxf(hi, 0.f);
    }

    float o0 = B3s[0], o1 = B3s[1];
    #pragma unroll
    for (int k = 0; k < 40; ++k) {
        o0 = fmaf(a2[k], W3s[2*k + 0], o0);
        o1 = fmaf(a2[k], W3s[2*k + 1], o1);
    }
    float2 ov = make_float2(o0, o1);
    *(float2*)(&out[((size_t)(b0 + tid) * T_STEPS + t) * 2]) = ov;
}

// ============================================================================
extern "C" void kernel_launch(void* const* d_in, const int* in_sizes, int n_in,
                              void* d_out, int out_size)
{
    const float* x     = (const float*)d_in[0];
    const float* fw_W1 = (const float*)d_in[1];
    const float* fw_b1 = (const float*)d_in[2];
    const float* fw_W2 = (const float*)d_in[3];
    const float* fw_b2 = (const float*)d_in[4];
    const float* bw_W1 = (const float*)d_in[5];
    const float* bw_b1 = (const float*)d_in[6];
    const float* bw_W2 = (const float*)d_in[7];
    const float* bw_b2 = (const float*)d_in[8];
    const float* Wf1   = (const float*)d_in[9];
    const float* bf1   = (const float*)d_in[10];
    const float* Wf2   = (const float*)d_in[11];
    const float* bf2   = (const float*)d_in[12];
    const float* Wf3   = (const float*)d_in[13];
    const float* bf3   = (const float*)d_in[14];

    cudaFuncSetAttribute(lstm_kernel, cudaFuncAttributeMaxDynamicSharedMemorySize,
                         SMEM_BYTES);
    cudaFuncSetAttribute(fc_kernel, cudaFuncAttributeMaxDynamicSharedMemorySize,
                         FSM_FLOATS * (int)sizeof(float));

    xsplit_kernel<<<dim3(T_STEPS, NBLK), TT>>>(x);

    lstm_kernel<<<dim3(NBLK, 2), NT, SMEM_BYTES>>>(
        fw_W1, fw_b1, fw_W2, fw_b2, bw_W1, bw_b1, bw_W2, bw_b2);

    fc_kernel<<<32 * T_STEPS, FCT, FSM_FLOATS * sizeof(float)>>>(
        Wf1, bf1, Wf2, bf2, Wf3, bf3, (float*)d_out);
}

// round 12
// speedup vs baseline: 1.7108x; 1.1573x over previous
#include <cuda_runtime.h>
#include <cuda_bf16.h>
#include <math.h>

#define T_STEPS 300
#define DIN 39
#define H1D 35
#define H2D 30
#define BT 64
#define BATCH 4096
#define NBLK (BATCH/BT)
#define NT 800           // 12 L1 warps + 12 L2 warps + 1 stager

#define KP 84            // row stride (bf16 elems) for A and W
#define N1 144           // L1 gate cols (36 units * 4)
#define N2 128           // L2 gate cols (32 units * 4)

// smem byte offsets (all 16B aligned)
#define B1_OFF   0
#define B2_OFF   576
#define W1H_OFF  1088
#define W1L_OFF  25280
#define W2H_OFF  49472
#define W2L_OFF  70976
#define A1H_OFF  92480     // 2 buffers of 64*KP u16 (10752 B each)
#define A1L_OFF  113984
#define A2H_OFF  135488
#define A2L_OFF  156992
#define SMEM_BYTES 178496
#define ABUF (64*KP)       // u16 elements per A buffer

typedef unsigned long long ull;
typedef unsigned short u16;
typedef unsigned int u32;

// scratch: LSTM hidden states [T][60][B]  (fw units [0,30), bw [30,60))
__device__ float g_hbuf[(size_t)BATCH * T_STEPS * 60];
// pre-split transposed input, A-operand layout [T][btile][64 rows][40 cols]
__device__ u16 g_xhi[(size_t)T_STEPS * NBLK * 64 * 40];
__device__ u16 g_xlo[(size_t)T_STEPS * NBLK * 64 * 40];

// ---------------- helpers ----------------
__device__ __forceinline__ ull fma2(ull a, ull b, ull c) {
    ull d;
    asm("fma.rn.f32x2 %0, %1, %2, %3;" : "=l"(d) : "l"(a), "l"(b), "l"(c));
    return d;
}
__device__ __forceinline__ ull pack2(float lo, float hi) {
    ull d;
    asm("mov.b64 %0, {%1, %2};" : "=l"(d) : "f"(lo), "f"(hi));
    return d;
}
__device__ __forceinline__ void unpack2(ull v, float& lo, float& hi) {
    asm("mov.b64 {%0, %1}, %2;" : "=f"(lo), "=f"(hi) : "l"(v));
}
__device__ __forceinline__ float sigf(float x) {
    return __fdividef(1.0f, 1.0f + __expf(-x));
}
__device__ __forceinline__ float tanhfast(float x) {
    return 2.0f * sigf(2.0f * x) - 1.0f;
}
__device__ __forceinline__ float cellone(float zi, float zj, float zf, float zo, float& c) {
    c = sigf(zf + 1.0f) * c + sigf(zi) * tanhfast(zj);
    return sigf(zo) * tanhfast(c);
}
__device__ __forceinline__ void bsplit(float v, u16& hi, u16& lo) {
    __nv_bfloat16 h = __float2bfloat16(v);
    float r = v - __bfloat162float(h);
    __nv_bfloat16 l = __float2bfloat16(r);
    hi = __bfloat16_as_ushort(h);
    lo = __bfloat16_as_ushort(l);
}

__device__ __forceinline__ void mma16816(float& c0, float& c1, float& c2, float& c3,
                                         u32 a0, u32 a1, u32 a2, u32 a3,
                                         u32 b0, u32 b1)
{
    asm volatile("mma.sync.aligned.m16n8k16.row.col.f32.bf16.bf16.f32 "
                 "{%0,%1,%2,%3},{%4,%5,%6,%7},{%8,%9},{%0,%1,%2,%3};"
                 : "+f"(c0), "+f"(c1), "+f"(c2), "+f"(c3)
                 : "r"(a0), "r"(a1), "r"(a2), "r"(a3), "r"(b0), "r"(b1));
}

// Fused MMA + cell for one warp covering m-tile mi, n-tiles n0..n0+NCNT.
// 3-product bf16 split GEMM (K=80) -> shfl gate exchange -> in-register cell
// -> bf16-split h write to A buffers (and optionally g_hbuf).
// Fragment map: acc[nt] = { z[r0][C+2tq], z[r0][C+2tq+1], z[r1][C+2tq], z[r1][C+2tq+1] }
//   r0 = mi*16+g, r1 = r0+8, C = (n0+nt)*8, g = lane>>2, tq = lane&3.
// Even tq handles (row r0, unit u); odd tq handles (row r1, unit u); u = 2*(n0+nt)+(tq>>1).
template<int NCNT>
__device__ __forceinline__ void mma_cell(
    const u16* __restrict__ Ah, const u16* __restrict__ Al,
    const u16* __restrict__ Wh, const u16* __restrict__ Wl,
    const float* __restrict__ bias, float* __restrict__ cst,
    u16* dA1h, u16* dA1l,            // null for L2
    u16* dA2h, u16* dA2l, int colbase,
    float* ghb,                       // null unless L2 (base for this tick)
    int mi, int n0, int lane)
{
    const int g  = lane >> 2;
    const int tq = lane & 3;
    const int t2 = tq * 2;
    float acc[NCNT][4];
    #pragma unroll
    for (int i = 0; i < NCNT; ++i) {
        acc[i][0] = 0.f; acc[i][1] = 0.f; acc[i][2] = 0.f; acc[i][3] = 0.f;
    }
    const int ar0 = (mi*16 + g)*KP + t2;
    const int ar1 = ar0 + 8*KP;
    #pragma unroll
    for (int kc = 0; kc < 5; ++kc) {
        const int ka = kc * 16;
        u32 ah0 = *(const u32*)(Ah + ar0 + ka);
        u32 ah1 = *(const u32*)(Ah + ar1 + ka);
        u32 ah2 = *(const u32*)(Ah + ar0 + ka + 8);
        u32 ah3 = *(const u32*)(Ah + ar1 + ka + 8);
        u32 al0 = *(const u32*)(Al + ar0 + ka);
        u32 al1 = *(const u32*)(Al + ar1 + ka);
        u32 al2 = *(const u32*)(Al + ar0 + ka + 8);
        u32 al3 = *(const u32*)(Al + ar1 + ka + 8);
        #pragma unroll
        for (int nt = 0; nt < NCNT; ++nt) {
            const int wr = ((n0 + nt)*8 + g)*KP + t2 + ka;
            u32 bh0 = *(const u32*)(Wh + wr);
            u32 bh1 = *(const u32*)(Wh + wr + 8);
            u32 bl0 = *(const u32*)(Wl + wr);
            u32 bl1 = *(const u32*)(Wl + wr + 8);
            mma16816(acc[nt][0],acc[nt][1],acc[nt][2],acc[nt][3], ah0,ah1,ah2,ah3, bh0,bh1);
            mma16816(acc[nt][0],acc[nt][1],acc[nt][2],acc[nt][3], ah0,ah1,ah2,ah3, bl0,bl1);
            mma16816(acc[nt][0],acc[nt][1],acc[nt][2],acc[nt][3], al0,al1,al2,al3, bh0,bh1);
        }
    }

    const int odd  = tq & 1;
    const int row  = (odd ? mi*16 + 8 : mi*16) + g;
    #pragma unroll
    for (int nt = 0; nt < NCNT; ++nt) {
        const int C = (n0 + nt) * 8;
        const int u = 2*(n0 + nt) + (tq >> 1);
        const float4 bb = *(const float4*)(bias + C + ((tq & 2) << 1));
        // exchange: even thread needs partner's acc0,acc1 (f,o of row r0);
        //           odd  thread needs partner's acc2,acc3 (i,j of row r1)
        float s0 = odd ? acc[nt][0] : acc[nt][2];
        float s1 = odd ? acc[nt][1] : acc[nt][3];
        float e0 = __shfl_xor_sync(0xffffffffu, s0, 1);
        float e1 = __shfl_xor_sync(0xffffffffu, s1, 1);
        float zi, zj, zf, zo;
        if (odd) { zi = e0;         zj = e1;         zf = acc[nt][2]; zo = acc[nt][3]; }
        else     { zi = acc[nt][0]; zj = acc[nt][1]; zf = e0;         zo = e1;         }
        float h = cellone(zi + bb.x, zj + bb.y, zf + bb.z, zo + bb.w, cst[nt]);
        u16 hh, hl; bsplit(h, hh, hl);
        const int idx = row*KP + colbase + u;
        dA2h[idx] = hh;
        dA2l[idx] = hl;
        if (dA1h) { dA1h[row*KP + u] = hh; dA1l[row*KP + u] = hl; }
        if (ghb && u < H2D) ghb[(size_t)u * BATCH + row] = h;
    }
}

// ============ x prep: [B][T][D] fp32 -> [T][btile][64][40] bf16 hi/lo ============
#define TT 256
__global__ void __launch_bounds__(TT)
xsplit_kernel(const float* __restrict__ x)
{
    __shared__ float s[DIN * 65];
    const int t  = blockIdx.x;
    const int bt = blockIdx.y;
    const int b0 = bt * 64;
    const int tid = threadIdx.x;

    for (int i = tid; i < 64 * DIN; i += TT) {
        int b = i / DIN, d = i - b * DIN;
        s[d * 65 + b] = x[((size_t)(b0 + b) * T_STEPS + t) * DIN + d];
    }
    __syncthreads();
    const size_t base = ((size_t)t * NBLK + bt) * 2560;
    for (int i = tid; i < 2560; i += TT) {
        int b = i / 40, d = i - b * 40;
        float v = (d < DIN) ? s[d * 65 + b] : 0.f;
        u16 hi, lo; bsplit(v, hi, lo);
        g_xhi[base + i] = hi;
        g_xlo[base + i] = lo;
    }
}

// =============================== LSTM kernel ===============================
extern __shared__ char smc[];

__global__ void __launch_bounds__(NT)
lstm_kernel(const float* __restrict__ fw_W1, const float* __restrict__ fw_b1,
            const float* __restrict__ fw_W2, const float* __restrict__ fw_b2,
            const float* __restrict__ bw_W1, const float* __restrict__ bw_b1,
            const float* __restrict__ bw_W2, const float* __restrict__ bw_b2)
{
    const int dir = blockIdx.y;
    const int bti = blockIdx.x;
    const int b0g = bti * BT;
    const int tid = threadIdx.x;

    float* b1s = (float*)(smc + B1_OFF);
    float* b2s = (float*)(smc + B2_OFF);
    u16* W1h = (u16*)(smc + W1H_OFF);
    u16* W1l = (u16*)(smc + W1L_OFF);
    u16* W2h = (u16*)(smc + W2H_OFF);
    u16* W2l = (u16*)(smc + W2L_OFF);
    u16* A1h = (u16*)(smc + A1H_OFF);   // [2][64*KP]
    u16* A1l = (u16*)(smc + A1L_OFF);
    u16* A2h = (u16*)(smc + A2H_OFF);
    u16* A2l = (u16*)(smc + A2L_OFF);

    const float* W1g = dir ? bw_W1 : fw_W1;
    const float* b1g = dir ? bw_b1 : fw_b1;
    const float* W2g = dir ? bw_W2 : fw_W2;
    const float* b2g = dir ? bw_b2 : fw_b2;

    // ---- prologue ----
    for (int i = tid; i < 2*ABUF; i += NT) { A1h[i]=0; A1l[i]=0; A2h[i]=0; A2l[i]=0; }

    // W1: n-major cols 0..143 (unit-major gates); k-rows: 0..34 h1, 35 pad, 36..74 x, 75..83 pad
    for (int i = tid; i < N1*KP; i += NT) {
        int n = i / KP, c = i - n * KP;
        int u = n >> 2, gg = n & 3;
        float v = 0.f;
        if (u < H1D) {
            int col = gg*H1D + u;
            int kr = -1;
            if (c < H1D) kr = 39 + c;
            else if (c >= 36 && c < 36 + DIN) kr = c - 36;
            if (kr >= 0) v = W1g[kr*140 + col];
        }
        u16 hi, lo; bsplit(v, hi, lo);
        W1h[i] = hi; W1l[i] = lo;
    }
    // W2: cols 0..127; k-rows: 0..34 h1, 35 pad, 36..65 h2, 66..83 pad
    for (int i = tid; i < N2*KP; i += NT) {
        int n = i / KP, c = i - n * KP;
        int u = n >> 2, gg = n & 3;
        float v = 0.f;
        if (u < H2D) {
            int col = gg*H2D + u;
            int kr = -1;
            if (c < H1D) kr = c;
            else if (c >= 36 && c < 36 + H2D) kr = H1D + (c - 36);
            if (kr >= 0) v = W2g[kr*120 + col];
        }
        u16 hi, lo; bsplit(v, hi, lo);
        W2h[i] = hi; W2l[i] = lo;
    }
    for (int i = tid; i < N1; i += NT) {
        int u = i >> 2, gg = i & 3;
        b1s[i] = (u < H1D) ? b1g[gg*H1D + u] : 0.f;
    }
    for (int i = tid; i < N2; i += NT) {
        int u = i >> 2, gg = i & 3;
        b2s[i] = (u < H2D) ? b2g[gg*H2D + u] : 0.f;
    }
    // stage x[0] into A1 buffer 1 (= read buffer of tick 0)
    {
        const int tx0 = dir ? (T_STEPS - 1) : 0;
        const size_t base = ((size_t)tx0 * NBLK + bti) * 2560;
        for (int i = tid; i < 2560; i += NT) {
            int r = i / 40, d = i - r * 40;
            A1h[ABUF + r*KP + 36 + d] = g_xhi[base + i];
            A1l[ABUF + r*KP + 36 + d] = g_xlo[base + i];
        }
    }
    __syncthreads();

    const int warp = tid >> 5, lane = tid & 31;
    float cst[6] = {0.f,0.f,0.f,0.f,0.f,0.f};

    // roles: warps 0..11 = L1 (mi = w&3, ngp = w>>2, NCNT=6, n0=ngp*6)
    //        warps 12..23 = L2 (w2=w-12: mi = w2&3, ngp = w2>>2; NCNT 6,5,5; n0 0,6,11)
    //        warp 24 = x stager
    for (int tk = 0; tk <= T_STEPS; ++tk) {
        const int wb = tk & 1, rb = wb ^ 1;

        if (warp < 12) {
            if (tk < T_STEPS) {
                const int mi = warp & 3, ngp = warp >> 2;
                mma_cell<6>(A1h + rb*ABUF, A1l + rb*ABUF, W1h, W1l,
                            b1s, cst,
                            A1h + wb*ABUF, A1l + wb*ABUF,
                            A2h + wb*ABUF, A2l + wb*ABUF, 0,
                            (float*)0, mi, ngp*6, lane);
            }
        } else if (warp < 24) {
            if (tk >= 1) {
                const int w2 = warp - 12;
                const int mi = w2 & 3, ngp = w2 >> 2;
                const int tx = dir ? (T_STEPS - tk) : (tk - 1);
                float* ghb = g_hbuf + ((size_t)(tx*60 + dir*H2D))*BATCH + b0g;
                if (ngp == 0)
                    mma_cell<6>(A2h + rb*ABUF, A2l + rb*ABUF, W2h, W2l,
                                b2s, cst, (u16*)0, (u16*)0,
                                A2h + wb*ABUF, A2l + wb*ABUF, 36,
                                ghb, mi, 0, lane);
                else if (ngp == 1)
                    mma_cell<5>(A2h + rb*ABUF, A2l + rb*ABUF, W2h, W2l,
                                b2s, cst, (u16*)0, (u16*)0,
                                A2h + wb*ABUF, A2l + wb*ABUF, 36,
                                ghb, mi, 6, lane);
                else
                    mma_cell<5>(A2h + rb*ABUF, A2l + rb*ABUF, W2h, W2l,
                                b2s, cst, (u16*)0, (u16*)0,
                                A2h + wb*ABUF, A2l + wb*ABUF, 36,
                                ghb, mi, 11, lane);
            }
        } else {
            if (tk + 1 < T_STEPS) {
                // stage x[tk+1] into A1[wb] x-region (read next tick)
                const int txn = dir ? (T_STEPS - 2 - tk) : (tk + 1);
                const size_t base = ((size_t)txn * NBLK + bti) * 2560;
                u16* dh = A1h + wb*ABUF;
                u16* dl = A1l + wb*ABUF;
                for (int i = lane; i < 640; i += 32) {
                    int r = i / 10, c = i - r * 10;
                    ((ull*)(dh + r*KP + 36))[c] = ((const ull*)(g_xhi + base + r*40))[c];
                    ((ull*)(dl + r*KP + 36))[c] = ((const ull*)(g_xlo + base + r*40))[c];
                }
            }
        }
        __syncthreads();
    }
}

// =============================== FC head (unchanged, passing) ===============================
#define FCT 128
#define FOFF_W1 0
#define FOFF_W2 (FOFF_W1 + 60*52)
#define FOFF_W3 (FOFF_W2 + 50*40)
#define FOFF_B1 (FOFF_W3 + 80)
#define FOFF_B2 (FOFF_B1 + 52)
#define FOFF_B3 (FOFF_B2 + 40)
#define FSM_FLOATS (FOFF_B3 + 4)

__global__ void __launch_bounds__(FCT)
fc_kernel(const float* __restrict__ Wf1, const float* __restrict__ bf1,
          const float* __restrict__ Wf2, const float* __restrict__ bf2,
          const float* __restrict__ Wf3, const float* __restrict__ bf3,
          float* __restrict__ out)
{
    extern __shared__ float fsm[];
    float* W1s = fsm + FOFF_W1;
    float* W2s = fsm + FOFF_W2;
    float* W3s = fsm + FOFF_W3;
    float* B1s = fsm + FOFF_B1;
    float* B2s = fsm + FOFF_B2;
    float* B3s = fsm + FOFF_B3;

    const int tid = threadIdx.x;

    for (int i = tid; i < 60*52; i += FCT) {
        int k = i / 52, j = i - k * 52;
        W1s[i] = (j < 50) ? Wf1[k*50 + j] : 0.f;
    }
    for (int i = tid; i < 50*40; i += FCT) W2s[i] = Wf2[i];
    for (int i = tid; i < 80;    i += FCT) W3s[i] = Wf3[i];
    for (int i = tid; i < 52;    i += FCT) B1s[i] = (i < 50) ? bf1[i] : 0.f;
    for (int i = tid; i < 40;    i += FCT) B2s[i] = bf2[i];
    for (int i = tid; i < 2;     i += FCT) B3s[i] = bf3[i];
    __syncthreads();

    const int bi = blockIdx.x & 31;
    const int t  = blockIdx.x >> 5;
    const int b0 = bi * FCT;
    const float* __restrict__ hb = &g_hbuf[(size_t)t * 60 * BATCH + b0 + tid];

    ull acc1[26];
    #pragma unroll
    for (int j = 0; j < 26; ++j) acc1[j] = pack2(B1s[2*j], B1s[2*j+1]);
    #pragma unroll 4
    for (int k = 0; k < 60; ++k) {
        float v = hb[(size_t)k * BATCH];
        ull vv = pack2(v, v);
        #pragma unroll
        for (int j = 0; j < 13; ++j) {
            ulonglong2 w = *(const ulonglong2*)(W1s + k*52 + j*4);
            acc1[2*j]   = fma2(vv, w.x, acc1[2*j]);
            acc1[2*j+1] = fma2(vv, w.y, acc1[2*j+1]);
        }
    }
    float a1[52];
    #pragma unroll
    for (int j = 0; j < 26; ++j) {
        float lo, hi; unpack2(acc1[j], lo, hi);
        a1[2*j]   = fmaxf(lo, 0.f);
        a1[2*j+1] = fmaxf(hi, 0.f);
    }

    ull acc2[20];
    #pragma unroll
    for (int j = 0; j < 20; ++j) acc2[j] = pack2(B2s[2*j], B2s[2*j+1]);
    #pragma unroll 5
    for (int k = 0; k < 50; ++k) {
        ull vv = pack2(a1[k], a1[k]);
        #pragma unroll
        for (int j = 0; j < 10; ++j) {
            ulonglong2 w = *(const ulonglong2*)(W2s + k*40 + j*4);
            acc2[2*j]   = fma2(vv, w.x, acc2[2*j]);
            acc2[2*j+1] = fma2(vv, w.y, acc2[2*j+1]);
        }
    }
    float a2[40];
    #pragma unroll
    for (int j = 0; j < 20; ++j) {
        float lo, hi; unpack2(acc2[j], lo, hi);
        a2[2*j]   = fmaxf(lo, 0.f);
        a2[2*j+1] = fmaxf(hi, 0.f);
    }

    float o0 = B3s[0], o1 = B3s[1];
    #pragma unroll
    for (int k = 0; k < 40; ++k) {
        o0 = fmaf(a2[k], W3s[2*k + 0], o0);
        o1 = fmaf(a2[k], W3s[2*k + 1], o1);
    }
    float2 ov = make_float2(o0, o1);
    *(float2*)(&out[((size_t)(b0 + tid) * T_STEPS + t) * 2]) = ov;
}

// ============================================================================
extern "C" void kernel_launch(void* const* d_in, const int* in_sizes, int n_in,
                              void* d_out, int out_size)
{
    const float* x     = (const float*)d_in[0];
    const float* fw_W1 = (const float*)d_in[1];
    const float* fw_b1 = (const float*)d_in[2];
    const float* fw_W2 = (const float*)d_in[3];
    const float* fw_b2 = (const float*)d_in[4];
    const float* bw_W1 = (const float*)d_in[5];
    const float* bw_b1 = (const float*)d_in[6];
    const float* bw_W2 = (const float*)d_in[7];
    const float* bw_b2 = (const float*)d_in[8];
    const float* Wf1   = (const float*)d_in[9];
    const float* bf1   = (const float*)d_in[10];
    const float* Wf2   = (const float*)d_in[11];
    const float* bf2   = (const float*)d_in[12];
    const float* Wf3   = (const float*)d_in[13];
    const float* bf3   = (const float*)d_in[14];

    cudaFuncSetAttribute(lstm_kernel, cudaFuncAttributeMaxDynamicSharedMemorySize,
                         SMEM_BYTES);
    cudaFuncSetAttribute(fc_kernel, cudaFuncAttributeMaxDynamicSharedMemorySize,
                         FSM_FLOATS * (int)sizeof(float));

    xsplit_kernel<<<dim3(T_STEPS, NBLK), TT>>>(x);

    lstm_kernel<<<dim3(NBLK, 2), NT, SMEM_BYTES>>>(
        fw_W1, fw_b1, fw_W2, fw_b2, bw_W1, bw_b1, bw_W2, bw_b2);

    fc_kernel<<<32 * T_STEPS, FCT, FSM_FLOATS * sizeof(float)>>>(
        Wf1, bf1, Wf2, bf2, Wf3, bf3, (float*)d_out);
}

// round 13
// speedup vs baseline: 1.9854x; 1.1605x over previous
#include <cuda_runtime.h>
#include <cuda_bf16.h>
#include <math.h>

#define T_STEPS 300
#define DIN 39
#define H1D 35
#define H2D 30
#define BT 64
#define BATCH 4096
#define NBLK (BATCH/BT)
#define NT 800           // 12 L1 warps + 12 L2 warps + 1 stager

#define KP 88            // row stride (bf16 elems): (row*44+tq)%32 covers all banks -> conflict-free
#define N1 144           // L1 gate cols (36 units * 4)
#define N2 128           // L2 gate cols (32 units * 4)

// smem byte offsets (all 16B aligned)
#define B1_OFF   0
#define B2_OFF   576
#define W1H_OFF  1088
#define W1L_OFF  26432
#define W2H_OFF  51776
#define W2L_OFF  74304
#define A1H_OFF  96832     // 2 buffers of 64*KP u16 (11264 B each)
#define A1L_OFF  119360
#define A2H_OFF  141888
#define A2L_OFF  164416
#define SMEM_BYTES 186944
#define ABUF (64*KP)       // u16 elements per A buffer

typedef unsigned long long ull;
typedef unsigned short u16;
typedef unsigned int u32;

// scratch: LSTM hidden states [T][60][B]  (fw units [0,30), bw [30,60))
__device__ float g_hbuf[(size_t)BATCH * T_STEPS * 60];
// pre-split transposed input, A-operand layout [T][btile][64 rows][40 cols]
__device__ u16 g_xhi[(size_t)T_STEPS * NBLK * 64 * 40];
__device__ u16 g_xlo[(size_t)T_STEPS * NBLK * 64 * 40];

// ---------------- helpers ----------------
__device__ __forceinline__ ull fma2(ull a, ull b, ull c) {
    ull d;
    asm("fma.rn.f32x2 %0, %1, %2, %3;" : "=l"(d) : "l"(a), "l"(b), "l"(c));
    return d;
}
__device__ __forceinline__ ull pack2(float lo, float hi) {
    ull d;
    asm("mov.b64 %0, {%1, %2};" : "=l"(d) : "f"(lo), "f"(hi));
    return d;
}
__device__ __forceinline__ void unpack2(ull v, float& lo, float& hi) {
    asm("mov.b64 {%0, %1}, %2;" : "=f"(lo), "=f"(hi) : "l"(v));
}
__device__ __forceinline__ float sigf(float x) {
    return __fdividef(1.0f, 1.0f + __expf(-x));
}
__device__ __forceinline__ float tanhfast(float x) {
    return 2.0f * sigf(2.0f * x) - 1.0f;
}
__device__ __forceinline__ float cellone(float zi, float zj, float zf, float zo, float& c) {
    c = sigf(zf + 1.0f) * c + sigf(zi) * tanhfast(zj);
    return sigf(zo) * tanhfast(c);
}
__device__ __forceinline__ void bsplit(float v, u16& hi, u16& lo) {
    __nv_bfloat16 h = __float2bfloat16(v);
    float r = v - __bfloat162float(h);
    __nv_bfloat16 l = __float2bfloat16(r);
    hi = __bfloat16_as_ushort(h);
    lo = __bfloat16_as_ushort(l);
}

__device__ __forceinline__ void mma16816(float& c0, float& c1, float& c2, float& c3,
                                         u32 a0, u32 a1, u32 a2, u32 a3,
                                         u32 b0, u32 b1)
{
    asm volatile("mma.sync.aligned.m16n8k16.row.col.f32.bf16.bf16.f32 "
                 "{%0,%1,%2,%3},{%4,%5,%6,%7},{%8,%9},{%0,%1,%2,%3};"
                 : "+f"(c0), "+f"(c1), "+f"(c2), "+f"(c3)
                 : "r"(a0), "r"(a1), "r"(a2), "r"(a3), "r"(b0), "r"(b1));
}

// Fused MMA + cell for one warp covering m-tile mi, n-tiles n0..n0+NCNT.
// 3-product bf16 split GEMM (K=80) -> shfl gate exchange -> in-register cell
// -> bf16-split h write to A buffers (and optionally g_hbuf).
template<int NCNT>
__device__ __forceinline__ void mma_cell(
    const u16* __restrict__ Ah, const u16* __restrict__ Al,
    const u16* __restrict__ Wh, const u16* __restrict__ Wl,
    const float* __restrict__ bias, float* __restrict__ cst,
    u16* dA1h, u16* dA1l,            // null for L2
    u16* dA2h, u16* dA2l, int colbase,
    float* ghb,                       // null unless L2 (base for this tick)
    int mi, int n0, int lane)
{
    const int g  = lane >> 2;
    const int tq = lane & 3;
    const int t2 = tq * 2;
    float acc[NCNT][4];
    #pragma unroll
    for (int i = 0; i < NCNT; ++i) {
        acc[i][0] = 0.f; acc[i][1] = 0.f; acc[i][2] = 0.f; acc[i][3] = 0.f;
    }
    const int ar0 = (mi*16 + g)*KP + t2;
    const int ar1 = ar0 + 8*KP;
    #pragma unroll
    for (int kc = 0; kc < 5; ++kc) {
        const int ka = kc * 16;
        u32 ah0 = *(const u32*)(Ah + ar0 + ka);
        u32 ah1 = *(const u32*)(Ah + ar1 + ka);
        u32 ah2 = *(const u32*)(Ah + ar0 + ka + 8);
        u32 ah3 = *(const u32*)(Ah + ar1 + ka + 8);
        u32 al0 = *(const u32*)(Al + ar0 + ka);
        u32 al1 = *(const u32*)(Al + ar1 + ka);
        u32 al2 = *(const u32*)(Al + ar0 + ka + 8);
        u32 al3 = *(const u32*)(Al + ar1 + ka + 8);
        #pragma unroll
        for (int nt = 0; nt < NCNT; ++nt) {
            const int wr = ((n0 + nt)*8 + g)*KP + t2 + ka;
            u32 bh0 = *(const u32*)(Wh + wr);
            u32 bh1 = *(const u32*)(Wh + wr + 8);
            u32 bl0 = *(const u32*)(Wl + wr);
            u32 bl1 = *(const u32*)(Wl + wr + 8);
            mma16816(acc[nt][0],acc[nt][1],acc[nt][2],acc[nt][3], ah0,ah1,ah2,ah3, bh0,bh1);
            mma16816(acc[nt][0],acc[nt][1],acc[nt][2],acc[nt][3], ah0,ah1,ah2,ah3, bl0,bl1);
            mma16816(acc[nt][0],acc[nt][1],acc[nt][2],acc[nt][3], al0,al1,al2,al3, bh0,bh1);
        }
    }

    const int odd  = tq & 1;
    const int row  = (odd ? mi*16 + 8 : mi*16) + g;
    #pragma unroll
    for (int nt = 0; nt < NCNT; ++nt) {
        const int C = (n0 + nt) * 8;
        const int u = 2*(n0 + nt) + (tq >> 1);
        const float4 bb = *(const float4*)(bias + C + ((tq & 2) << 1));
        float s0 = odd ? acc[nt][0] : acc[nt][2];
        float s1 = odd ? acc[nt][1] : acc[nt][3];
        float e0 = __shfl_xor_sync(0xffffffffu, s0, 1);
        float e1 = __shfl_xor_sync(0xffffffffu, s1, 1);
        float zi, zj, zf, zo;
        if (odd) { zi = e0;         zj = e1;         zf = acc[nt][2]; zo = acc[nt][3]; }
        else     { zi = acc[nt][0]; zj = acc[nt][1]; zf = e0;         zo = e1;         }
        float h = cellone(zi + bb.x, zj + bb.y, zf + bb.z, zo + bb.w, cst[nt]);
        u16 hh, hl; bsplit(h, hh, hl);
        const int idx = row*KP + colbase + u;
        dA2h[idx] = hh;
        dA2l[idx] = hl;
        if (dA1h) { dA1h[row*KP + u] = hh; dA1l[row*KP + u] = hl; }
        if (ghb && u < H2D) ghb[(size_t)u * BATCH + row] = h;
    }
}

// ============ x prep: [B][T][D] fp32 -> [T][btile][64][40] bf16 hi/lo ============
#define TT 256
__global__ void __launch_bounds__(TT)
xsplit_kernel(const float* __restrict__ x)
{
    __shared__ float s[DIN * 65];
    const int t  = blockIdx.x;
    const int bt = blockIdx.y;
    const int b0 = bt * 64;
    const int tid = threadIdx.x;

    for (int i = tid; i < 64 * DIN; i += TT) {
        int b = i / DIN, d = i - b * DIN;
        s[d * 65 + b] = x[((size_t)(b0 + b) * T_STEPS + t) * DIN + d];
    }
    __syncthreads();
    const size_t base = ((size_t)t * NBLK + bt) * 2560;
    for (int i = tid; i < 2560; i += TT) {
        int b = i / 40, d = i - b * 40;
        float v = (d < DIN) ? s[d * 65 + b] : 0.f;
        u16 hi, lo; bsplit(v, hi, lo);
        g_xhi[base + i] = hi;
        g_xlo[base + i] = lo;
    }
}

// =============================== LSTM kernel ===============================
extern __shared__ char smc[];

__global__ void __launch_bounds__(NT)
lstm_kernel(const float* __restrict__ fw_W1, const float* __restrict__ fw_b1,
            const float* __restrict__ fw_W2, const float* __restrict__ fw_b2,
            const float* __restrict__ bw_W1, const float* __restrict__ bw_b1,
            const float* __restrict__ bw_W2, const float* __restrict__ bw_b2)
{
    const int dir = blockIdx.y;
    const int bti = blockIdx.x;
    const int b0g = bti * BT;
    const int tid = threadIdx.x;

    float* b1s = (float*)(smc + B1_OFF);
    float* b2s = (float*)(smc + B2_OFF);
    u16* W1h = (u16*)(smc + W1H_OFF);
    u16* W1l = (u16*)(smc + W1L_OFF);
    u16* W2h = (u16*)(smc + W2H_OFF);
    u16* W2l = (u16*)(smc + W2L_OFF);
    u16* A1h = (u16*)(smc + A1H_OFF);   // [2][64*KP]
    u16* A1l = (u16*)(smc + A1L_OFF);
    u16* A2h = (u16*)(smc + A2H_OFF);
    u16* A2l = (u16*)(smc + A2L_OFF);

    const float* W1g = dir ? bw_W1 : fw_W1;
    const float* b1g = dir ? bw_b1 : fw_b1;
    const float* W2g = dir ? bw_W2 : fw_W2;
    const float* b2g = dir ? bw_b2 : fw_b2;

    // ---- prologue ----
    for (int i = tid; i < 2*ABUF; i += NT) { A1h[i]=0; A1l[i]=0; A2h[i]=0; A2l[i]=0; }

    // W1: n-major cols 0..143 (unit-major gates); k-rows: 0..34 h1, 35 pad, 36..74 x, 75..87 pad
    for (int i = tid; i < N1*KP; i += NT) {
        int n = i / KP, c = i - n * KP;
        int u = n >> 2, gg = n & 3;
        float v = 0.f;
        if (u < H1D) {
            int col = gg*H1D + u;
            int kr = -1;
            if (c < H1D) kr = 39 + c;
            else if (c >= 36 && c < 36 + DIN) kr = c - 36;
            if (kr >= 0) v = W1g[kr*140 + col];
        }
        u16 hi, lo; bsplit(v, hi, lo);
        W1h[i] = hi; W1l[i] = lo;
    }
    // W2: cols 0..127; k-rows: 0..34 h1, 35 pad, 36..65 h2, 66..87 pad
    for (int i = tid; i < N2*KP; i += NT) {
        int n = i / KP, c = i - n * KP;
        int u = n >> 2, gg = n & 3;
        float v = 0.f;
        if (u < H2D) {
            int col = gg*H2D + u;
            int kr = -1;
            if (c < H1D) kr = c;
            else if (c >= 36 && c < 36 + H2D) kr = H1D + (c - 36);
            if (kr >= 0) v = W2g[kr*120 + col];
        }
        u16 hi, lo; bsplit(v, hi, lo);
        W2h[i] = hi; W2l[i] = lo;
    }
    for (int i = tid; i < N1; i += NT) {
        int u = i >> 2, gg = i & 3;
        b1s[i] = (u < H1D) ? b1g[gg*H1D + u] : 0.f;
    }
    for (int i = tid; i < N2; i += NT) {
        int u = i >> 2, gg = i & 3;
        b2s[i] = (u < H2D) ? b2g[gg*H2D + u] : 0.f;
    }
    // stage x[0] into A1 buffer 1 (= read buffer of tick 0)
    {
        const int tx0 = dir ? (T_STEPS - 1) : 0;
        const size_t base = ((size_t)tx0 * NBLK + bti) * 2560;
        for (int i = tid; i < 2560; i += NT) {
            int r = i / 40, d = i - r * 40;
            A1h[ABUF + r*KP + 36 + d] = g_xhi[base + i];
            A1l[ABUF + r*KP + 36 + d] = g_xlo[base + i];
        }
    }
    __syncthreads();

    const int warp = tid >> 5, lane = tid & 31;
    float cst[6] = {0.f,0.f,0.f,0.f,0.f,0.f};

    // roles: warps 0..11 = L1 (mi = w&3, ngp = w>>2, NCNT=6, n0=ngp*6)
    //        warps 12..23 = L2 (w2=w-12: mi = w2&3, ngp = w2>>2; NCNT 6,5,5; n0 0,6,11)
    //        warp 24 = x stager
    for (int tk = 0; tk <= T_STEPS; ++tk) {
        const int wb = tk & 1, rb = wb ^ 1;

        if (warp < 12) {
            if (tk < T_STEPS) {
                const int mi = warp & 3, ngp = warp >> 2;
                mma_cell<6>(A1h + rb*ABUF, A1l + rb*ABUF, W1h, W1l,
                            b1s, cst,
                            A1h + wb*ABUF, A1l + wb*ABUF,
                            A2h + wb*ABUF, A2l + wb*ABUF, 0,
                            (float*)0, mi, ngp*6, lane);
            }
        } else if (warp < 24) {
            if (tk >= 1) {
                const int w2 = warp - 12;
                const int mi = w2 & 3, ngp = w2 >> 2;
                const int tx = dir ? (T_STEPS - tk) : (tk - 1);
                float* ghb = g_hbuf + ((size_t)(tx*60 + dir*H2D))*BATCH + b0g;
                if (ngp == 0)
                    mma_cell<6>(A2h + rb*ABUF, A2l + rb*ABUF, W2h, W2l,
                                b2s, cst, (u16*)0, (u16*)0,
                                A2h + wb*ABUF, A2l + wb*ABUF, 36,
                                ghb, mi, 0, lane);
                else if (ngp == 1)
                    mma_cell<5>(A2h + rb*ABUF, A2l + rb*ABUF, W2h, W2l,
                                b2s, cst, (u16*)0, (u16*)0,
                                A2h + wb*ABUF, A2l + wb*ABUF, 36,
                                ghb, mi, 6, lane);
                else
                    mma_cell<5>(A2h + rb*ABUF, A2l + rb*ABUF, W2h, W2l,
                                b2s, cst, (u16*)0, (u16*)0,
                                A2h + wb*ABUF, A2l + wb*ABUF, 36,
                                ghb, mi, 11, lane);
            }
        } else {
            if (tk + 1 < T_STEPS) {
                // stage x[tk+1] into A1[wb] x-region (read next tick)
                const int txn = dir ? (T_STEPS - 2 - tk) : (tk + 1);
                const size_t base = ((size_t)txn * NBLK + bti) * 2560;
                u16* dh = A1h + wb*ABUF;
                u16* dl = A1l + wb*ABUF;
                for (int i = lane; i < 640; i += 32) {
                    int r = i / 10, c = i - r * 10;
                    ((ull*)(dh + r*KP + 36))[c] = ((const ull*)(g_xhi + base + r*40))[c];
                    ((ull*)(dl + r*KP + 36))[c] = ((const ull*)(g_xlo + base + r*40))[c];
                }
            }
        }
        __syncthreads();
    }
}

// =============================== FC head (unchanged, passing) ===============================
#define FCT 128
#define FOFF_W1 0
#define FOFF_W2 (FOFF_W1 + 60*52)
#define FOFF_W3 (FOFF_W2 + 50*40)
#define FOFF_B1 (FOFF_W3 + 80)
#define FOFF_B2 (FOFF_B1 + 52)
#define FOFF_B3 (FOFF_B2 + 40)
#define FSM_FLOATS (FOFF_B3 + 4)

__global__ void __launch_bounds__(FCT)
fc_kernel(const float* __restrict__ Wf1, const float* __restrict__ bf1,
          const float* __restrict__ Wf2, const float* __restrict__ bf2,
          const float* __restrict__ Wf3, const float* __restrict__ bf3,
          float* __restrict__ out)
{
    extern __shared__ float fsm[];
    float* W1s = fsm + FOFF_W1;
    float* W2s = fsm + FOFF_W2;
    float* W3s = fsm + FOFF_W3;
    float* B1s = fsm + FOFF_B1;
    float* B2s = fsm + FOFF_B2;
    float* B3s = fsm + FOFF_B3;

    const int tid = threadIdx.x;

    for (int i = tid; i < 60*52; i += FCT) {
        int k = i / 52, j = i - k * 52;
        W1s[i] = (j < 50) ? Wf1[k*50 + j] : 0.f;
    }
    for (int i = tid; i < 50*40; i += FCT) W2s[i] = Wf2[i];
    for (int i = tid; i < 80;    i += FCT) W3s[i] = Wf3[i];
    for (int i = tid; i < 52;    i += FCT) B1s[i] = (i < 50) ? bf1[i] : 0.f;
    for (int i = tid; i < 40;    i += FCT) B2s[i] = bf2[i];
    for (int i = tid; i < 2;     i += FCT) B3s[i] = bf3[i];
    __syncthreads();

    const int bi = blockIdx.x & 31;
    const int t  = blockIdx.x >> 5;
    const int b0 = bi * FCT;
    const float* __restrict__ hb = &g_hbuf[(size_t)t * 60 * BATCH + b0 + tid];

    ull acc1[26];
    #pragma unroll
    for (int j = 0; j < 26; ++j) acc1[j] = pack2(B1s[2*j], B1s[2*j+1]);
    #pragma unroll 4
    for (int k = 0; k < 60; ++k) {
        float v = hb[(size_t)k * BATCH];
        ull vv = pack2(v, v);
        #pragma unroll
        for (int j = 0; j < 13; ++j) {
            ulonglong2 w = *(const ulonglong2*)(W1s + k*52 + j*4);
            acc1[2*j]   = fma2(vv, w.x, acc1[2*j]);
            acc1[2*j+1] = fma2(vv, w.y, acc1[2*j+1]);
        }
    }
    float a1[52];
    #pragma unroll
    for (int j = 0; j < 26; ++j) {
        float lo, hi; unpack2(acc1[j], lo, hi);
        a1[2*j]   = fmaxf(lo, 0.f);
        a1[2*j+1] = fmaxf(hi, 0.f);
    }

    ull acc2[20];
    #pragma unroll
    for (int j = 0; j < 20; ++j) acc2[j] = pack2(B2s[2*j], B2s[2*j+1]);
    #pragma unroll 5
    for (int k = 0; k < 50; ++k) {
        ull vv = pack2(a1[k], a1[k]);
        #pragma unroll
        for (int j = 0; j < 10; ++j) {
            ulonglong2 w = *(const ulonglong2*)(W2s + k*40 + j*4);
            acc2[2*j]   = fma2(vv, w.x, acc2[2*j]);
            acc2[2*j+1] = fma2(vv, w.y, acc2[2*j+1]);
        }
    }
    float a2[40];
    #pragma unroll
    for (int j = 0; j < 20; ++j) {
        float lo, hi; unpack2(acc2[j], lo, hi);
        a2[2*j]   = fmaxf(lo, 0.f);
        a2[2*j+1] = fmaxf(hi, 0.f);
    }

    float o0 = B3s[0], o1 = B3s[1];
    #pragma unroll
    for (int k = 0; k < 40; ++k) {
        o0 = fmaf(a2[k], W3s[2*k + 0], o0);
        o1 = fmaf(a2[k], W3s[2*k + 1], o1);
    }
    float2 ov = make_float2(o0, o1);
    *(float2*)(&out[((size_t)(b0 + tid) * T_STEPS + t) * 2]) = ov;
}

// ============================================================================
extern "C" void kernel_launch(void* const* d_in, const int* in_sizes, int n_in,
                              void* d_out, int out_size)
{
    const float* x     = (const float*)d_in[0];
    const float* fw_W1 = (const float*)d_in[1];
    const float* fw_b1 = (const float*)d_in[2];
    const float* fw_W2 = (const float*)d_in[3];
    const float* fw_b2 = (const float*)d_in[4];
    const float* bw_W1 = (const float*)d_in[5];
    const float* bw_b1 = (const float*)d_in[6];
    const float* bw_W2 = (const float*)d_in[7];
    const float* bw_b2 = (const float*)d_in[8];
    const float* Wf1   = (const float*)d_in[9];
    const float* bf1   = (const float*)d_in[10];
    const float* Wf2   = (const float*)d_in[11];
    const float* bf2   = (const float*)d_in[12];
    const float* Wf3   = (const float*)d_in[13];
    const float* bf3   = (const float*)d_in[14];

    cudaFuncSetAttribute(lstm_kernel, cudaFuncAttributeMaxDynamicSharedMemorySize,
                         SMEM_BYTES);
    cudaFuncSetAttribute(fc_kernel, cudaFuncAttributeMaxDynamicSharedMemorySize,
                         FSM_FLOATS * (int)sizeof(float));

    xsplit_kernel<<<dim3(T_STEPS, NBLK), TT>>>(x);

    lstm_kernel<<<dim3(NBLK, 2), NT, SMEM_BYTES>>>(
        fw_W1, fw_b1, fw_W2, fw_b2, bw_W1, bw_b1, bw_W2, bw_b2);

    fc_kernel<<<32 * T_STEPS, FCT, FSM_FLOATS * sizeof(float)>>>(
        Wf1, bf1, Wf2, bf2, Wf3, bf3, (float*)d_out);
}